// round 11
// baseline (speedup 1.0000x reference)
#include <cuda_runtime.h>
#include <cuda_bf16.h>
#include <math.h>
#include <stdint.h>

#define S 1024
#define D 1024
#define H 16
#define HD 64
#define L 4
#define FF 4096
#define V 32000
#define EPSF 1e-5f

// ---------------------------------------------------------------------------
// device scratch
// ---------------------------------------------------------------------------
__device__ __align__(16) float g_h[S * D];

__device__ __align__(16) __nv_bfloat16 g_act_h[S * FF];
__device__ __align__(16) __nv_bfloat16 g_act_l[S * FF];
__device__ __align__(16) __nv_bfloat16 g_ff_h[S * FF];
__device__ __align__(16) __nv_bfloat16 g_ff_l[S * FF];
__device__ __align__(16) __nv_bfloat16 g_qh[S * D];
__device__ __align__(16) __nv_bfloat16 g_ql[S * D];
__device__ __align__(16) __nv_bfloat16 g_kh[S * D];
__device__ __align__(16) __nv_bfloat16 g_kl[S * D];
__device__ __align__(16) __nv_bfloat16 g_vth[D * S];
__device__ __align__(16) __nv_bfloat16 g_vtl[D * S];

// weights: K-major [K,N] bf16 hi/lo
__device__ __align__(16) __nv_bfloat16 g_qkv_h[(size_t)L * 3 * D * D];
__device__ __align__(16) __nv_bfloat16 g_qkv_l[(size_t)L * 3 * D * D];
__device__ __align__(16) __nv_bfloat16 g_wo_h[(size_t)L * D * D];
__device__ __align__(16) __nv_bfloat16 g_wo_l[(size_t)L * D * D];
__device__ __align__(16) __nv_bfloat16 g_w1_h[(size_t)L * D * FF];
__device__ __align__(16) __nv_bfloat16 g_w1_l[(size_t)L * D * FF];
__device__ __align__(16) __nv_bfloat16 g_w2_h[(size_t)L * FF * D];
__device__ __align__(16) __nv_bfloat16 g_w2_l[(size_t)L * FF * D];
__device__ __align__(16) __nv_bfloat16 g_lm_h[(size_t)D * V];
__device__ __align__(16) __nv_bfloat16 g_lm_l[(size_t)D * V];

// ---------------------------------------------------------------------------
// PTX helpers
// ---------------------------------------------------------------------------
__device__ __forceinline__ uint32_t smem_u32(const void* p) {
    uint32_t a;
    asm("{ .reg .u64 t; cvta.to.shared.u64 t, %1; cvt.u32.u64 %0, t; }" : "=r"(a) : "l"(p));
    return a;
}
#define CP16(dst, src) \
    asm volatile("cp.async.cg.shared.global [%0], [%1], 16;" :: "r"(dst), "l"(src))
#define CP_COMMIT() asm volatile("cp.async.commit_group;" ::: "memory")
#define CP_WAIT(n)  asm volatile("cp.async.wait_group %0;" :: "n"(n) : "memory")

__device__ __forceinline__ void ldsm4(uint32_t* r, uint32_t addr) {
    asm volatile("ldmatrix.sync.aligned.m8n8.x4.shared.b16 {%0,%1,%2,%3}, [%4];"
                 : "=r"(r[0]), "=r"(r[1]), "=r"(r[2]), "=r"(r[3]) : "r"(addr));
}
__device__ __forceinline__ void ldsm4t(uint32_t* r, uint32_t addr) {
    asm volatile("ldmatrix.sync.aligned.m8n8.x4.trans.shared.b16 {%0,%1,%2,%3}, [%4];"
                 : "=r"(r[0]), "=r"(r[1]), "=r"(r[2]), "=r"(r[3]) : "r"(addr));
}
__device__ __forceinline__ void mma_bf16(float* d, const uint32_t* a, const uint32_t* b) {
    asm volatile(
        "mma.sync.aligned.m16n8k16.row.col.f32.bf16.bf16.f32 "
        "{%0,%1,%2,%3}, {%4,%5,%6,%7}, {%8,%9}, {%0,%1,%2,%3};"
        : "+f"(d[0]), "+f"(d[1]), "+f"(d[2]), "+f"(d[3])
        : "r"(a[0]), "r"(a[1]), "r"(a[2]), "r"(a[3]), "r"(b[0]), "r"(b[1]));
}
__device__ __forceinline__ uint32_t pack2bf(float a, float b) {
    unsigned short ra = __bfloat16_as_ushort(__float2bfloat16(a));
    unsigned short rb = __bfloat16_as_ushort(__float2bfloat16(b));
    return (uint32_t)ra | ((uint32_t)rb << 16);
}

// ---------------------------------------------------------------------------
// GEMM cores. A row-major hi/lo [M,K]; B K-major hi/lo [K,N]. 3-stage pipe.
// ---------------------------------------------------------------------------
#define MG_SMEM (3 * 32768)
#define T64_SMEM (3 * 16384)

__device__ __forceinline__ void tile_load_A(uint32_t sdst,
                                            const __nv_bfloat16* gh,
                                            const __nv_bfloat16* gl,
                                            int ld, int k0, int tid) {
#pragma unroll
    for (int i = 0; i < 4; i++) {
        int cid = i * 256 + tid;
        int row = cid >> 3, sub = cid & 7;
        const __nv_bfloat16* src =
            ((sub & 4) ? gl : gh) + (size_t)row * ld + k0 + (sub & 3) * 8;
        uint32_t dst = sdst + row * 128 + ((sub ^ (row & 7)) << 4);
        CP16(dst, src);
    }
}

__device__ __forceinline__ void tile_load_A64(uint32_t sdst,
                                              const __nv_bfloat16* gh,
                                              const __nv_bfloat16* gl,
                                              int ld, int k0, int tid) {
#pragma unroll
    for (int i = 0; i < 2; i++) {
        int cid = i * 256 + tid;
        int row = cid >> 3, sub = cid & 7;
        const __nv_bfloat16* src =
            ((sub & 4) ? gl : gh) + (size_t)row * ld + k0 + (sub & 3) * 8;
        uint32_t dst = sdst + row * 128 + ((sub ^ (row & 7)) << 4);
        CP16(dst, src);
    }
}

__device__ __forceinline__ void tile_load_B(uint32_t sdst,
                                            const __nv_bfloat16* gh,
                                            const __nv_bfloat16* gl,
                                            int ldb, int bn, int k0, int tid) {
#pragma unroll
    for (int i = 0; i < 4; i++) {
        int cid = i * 256 + tid;
        int half = cid >> 9;
        int rem = cid & 511;
        int row = rem >> 4, c = rem & 15;
        const __nv_bfloat16* src =
            (half ? gl : gh) + (size_t)(k0 + row) * ldb + bn + c * 8;
        uint32_t dst = sdst + half * 8192 + row * 256 +
                       ((c ^ ((row & 7) << 1)) << 4);
        CP16(dst, src);
    }
}

__device__ __forceinline__ void tile_load_B64(uint32_t sdst,
                                              const __nv_bfloat16* gh,
                                              const __nv_bfloat16* gl,
                                              int ldb, int bn, int k0, int tid) {
#pragma unroll
    for (int i = 0; i < 2; i++) {
        int cid = i * 256 + tid;
        int half = cid >> 8;
        int rem = cid & 255;
        int row = rem >> 3, c = rem & 7;
        const __nv_bfloat16* src =
            (half ? gl : gh) + (size_t)(k0 + row) * ldb + bn + c * 8;
        uint32_t dst = sdst + half * 4096 + row * 128 + ((c ^ (row & 7)) << 4);
        CP16(dst, src);
    }
}

__device__ __forceinline__ void gemm_core(float (&acc)[4][4][4],
                                          const __nv_bfloat16* Ah, const __nv_bfloat16* Al,
                                          const __nv_bfloat16* Bh, const __nv_bfloat16* Bl,
                                          int K, int ldb, int bm, int bn, char* smem) {
    const int tid = threadIdx.x;
    const int wid = tid >> 5, lane = tid & 31;
    const int wm = (wid >> 2) * 64, wn = (wid & 3) * 32;
    uint32_t sbase = smem_u32(smem);

    const __nv_bfloat16* ah_g = Ah + (size_t)bm * K;
    const __nv_bfloat16* al_g = Al + (size_t)bm * K;

    const int nt = K >> 5;
    tile_load_A(sbase, ah_g, al_g, K, 0, tid);
    tile_load_B(sbase + 16384, Bh, Bl, ldb, bn, 0, tid);
    CP_COMMIT();
    tile_load_A(sbase + 32768, ah_g, al_g, K, 32, tid);
    tile_load_B(sbase + 32768 + 16384, Bh, Bl, ldb, bn, 32, tid);
    CP_COMMIT();

    const int kr_base = (lane & 7) + ((lane >> 3) & 1) * 8;
    const int nc8 = (lane >> 4);

    int br = 0, bw = 2;
    for (int t = 0; t < nt; t++) {
        if (t + 1 < nt) { CP_WAIT(1); } else { CP_WAIT(0); }
        __syncthreads();
        if (t + 2 < nt) {
            uint32_t nb = sbase + bw * 32768;
            tile_load_A(nb, ah_g, al_g, K, (t + 2) << 5, tid);
            tile_load_B(nb + 16384, Bh, Bl, ldb, bn, (t + 2) << 5, tid);
            CP_COMMIT();
        }

        uint32_t sA = sbase + br * 32768;
        uint32_t sB = sA + 16384;
#pragma unroll
        for (int ks = 0; ks < 2; ks++) {
            uint32_t bhf[2][4], blf[2][4];
#pragma unroll
            for (int np = 0; np < 2; np++) {
                int krow = ks * 16 + kr_base;
                int ncol = wn + np * 16 + nc8 * 8;
                int c = ncol >> 3;
                uint32_t a = sB + krow * 256 + ((c ^ ((krow & 7) << 1)) << 4);
                ldsm4t(bhf[np], a);
                ldsm4t(blf[np], a + 8192);
            }
#pragma unroll
            for (int mp = 0; mp < 2; mp++) {
                uint32_t ahf[2][4], alf[2][4];
#pragma unroll
                for (int f2 = 0; f2 < 2; f2++) {
                    int row = wm + (mp * 2 + f2) * 16 + (lane & 15);
                    int jc = (lane >> 4) + ks * 2;
                    ldsm4(ahf[f2], sA + row * 128 + ((jc ^ (row & 7)) << 4));
                    ldsm4(alf[f2], sA + row * 128 + (((jc + 4) ^ (row & 7)) << 4));
                }
#pragma unroll
                for (int m2 = 0; m2 < 2; m2++)
#pragma unroll
                    for (int nf = 0; nf < 4; nf++) {
                        uint32_t* bhp = &bhf[nf >> 1][(nf & 1) * 2];
                        uint32_t* blp = &blf[nf >> 1][(nf & 1) * 2];
                        float* ac = acc[mp * 2 + m2][nf];
                        mma_bf16(ac, ahf[m2], bhp);
                        mma_bf16(ac, ahf[m2], blp);
                        mma_bf16(ac, alf[m2], bhp);
                    }
            }
        }
        br = (br == 2) ? 0 : br + 1;
        bw = (bw == 2) ? 0 : bw + 1;
    }
}

__device__ __forceinline__ void gemm_core_t64(float (&acc)[4][4],
                                              const __nv_bfloat16* Ah, const __nv_bfloat16* Al,
                                              const __nv_bfloat16* Bh, const __nv_bfloat16* Bl,
                                              int K, int ldb, int bm, int bn, char* smem) {
    const int tid = threadIdx.x;
    const int wid = tid >> 5, lane = tid & 31;
    const int wm = (wid >> 1) * 16, wn = (wid & 1) * 32;
    uint32_t sbase = smem_u32(smem);

    const __nv_bfloat16* ah_g = Ah + (size_t)bm * K;
    const __nv_bfloat16* al_g = Al + (size_t)bm * K;

    const int nt = K >> 5;
    tile_load_A64(sbase, ah_g, al_g, K, 0, tid);
    tile_load_B64(sbase + 8192, Bh, Bl, ldb, bn, 0, tid);
    CP_COMMIT();
    tile_load_A64(sbase + 16384, ah_g, al_g, K, 32, tid);
    tile_load_B64(sbase + 16384 + 8192, Bh, Bl, ldb, bn, 32, tid);
    CP_COMMIT();

    const int kr_base = (lane & 7) + ((lane >> 3) & 1) * 8;
    const int nc8 = (lane >> 4);

    int br = 0, bw = 2;
    for (int t = 0; t < nt; t++) {
        if (t + 1 < nt) { CP_WAIT(1); } else { CP_WAIT(0); }
        __syncthreads();
        if (t + 2 < nt) {
            uint32_t nb = sbase + bw * 16384;
            tile_load_A64(nb, ah_g, al_g, K, (t + 2) << 5, tid);
            tile_load_B64(nb + 8192, Bh, Bl, ldb, bn, (t + 2) << 5, tid);
            CP_COMMIT();
        }

        uint32_t sA = sbase + br * 16384;
        uint32_t sB = sA + 8192;
#pragma unroll
        for (int ks = 0; ks < 2; ks++) {
            uint32_t bhf[2][4], blf[2][4];
#pragma unroll
            for (int np = 0; np < 2; np++) {
                int krow = ks * 16 + kr_base;
                int ncol = wn + np * 16 + nc8 * 8;
                int c = ncol >> 3;
                uint32_t a = sB + krow * 128 + ((c ^ (krow & 7)) << 4);
                ldsm4t(bhf[np], a);
                ldsm4t(blf[np], a + 4096);
            }
            uint32_t ahf[4], alf[4];
            {
                int row = wm + (lane & 15);
                int jc = (lane >> 4) + ks * 2;
                ldsm4(ahf, sA + row * 128 + ((jc ^ (row & 7)) << 4));
                ldsm4(alf, sA + row * 128 + (((jc + 4) ^ (row & 7)) << 4));
            }
#pragma unroll
            for (int nf = 0; nf < 4; nf++) {
                uint32_t* bhp = &bhf[nf >> 1][(nf & 1) * 2];
                uint32_t* blp = &blf[nf >> 1][(nf & 1) * 2];
                float* ac = acc[nf];
                mma_bf16(ac, ahf, bhp);
                mma_bf16(ac, ahf, blp);
                mma_bf16(ac, alf, bhp);
            }
        }
        br = (br == 2) ? 0 : br + 1;
        bw = (bw == 2) ? 0 : bw + 1;
    }
}

// fp32 output (+bias, +res), 128-wide N
__global__ __launch_bounds__(256, 2)
void k_gemm_f32(const __nv_bfloat16* __restrict__ Ah, const __nv_bfloat16* __restrict__ Al,
                const __nv_bfloat16* __restrict__ Bh, const __nv_bfloat16* __restrict__ Bl,
                const float* __restrict__ bias, const float* __restrict__ res,
                float* __restrict__ C, int K, int ldb, int ldc) {
    extern __shared__ char smem[];
    const int tid = threadIdx.x, wid = tid >> 5, lane = tid & 31;
    const int bm = blockIdx.y * 128, bn = blockIdx.x * 128;
    const int wm = (wid >> 2) * 64, wn = (wid & 3) * 32;
    float acc[4][4][4] = {};
    gemm_core(acc, Ah, Al, Bh, Bl, K, ldb, bm, bn, smem);
#pragma unroll
    for (int m = 0; m < 4; m++) {
        int r0 = bm + wm + m * 16 + (lane >> 2);
#pragma unroll
        for (int nf = 0; nf < 4; nf++) {
            int col = bn + wn + nf * 8 + ((lane & 3) << 1);
            float v0 = acc[m][nf][0], v1 = acc[m][nf][1];
            float v2 = acc[m][nf][2], v3 = acc[m][nf][3];
            if (bias) {
                float b0 = bias[col], b1 = bias[col + 1];
                v0 += b0; v1 += b1; v2 += b0; v3 += b1;
            }
            if (res) {
                const float* rr0 = res + (size_t)r0 * ldc + col;
                const float* rr1 = res + (size_t)(r0 + 8) * ldc + col;
                v0 += rr0[0]; v1 += rr0[1]; v2 += rr1[0]; v3 += rr1[1];
            }
            *(float2*)(C + (size_t)r0 * ldc + col) = make_float2(v0, v1);
            *(float2*)(C + (size_t)(r0 + 8) * ldc + col) = make_float2(v2, v3);
        }
    }
}

// fp32 output (+bias, +res), 64x64 tile — Wo / FFN2
__global__ __launch_bounds__(256, 2)
void k_gemm_f32_t64(const __nv_bfloat16* __restrict__ Ah, const __nv_bfloat16* __restrict__ Al,
                    const __nv_bfloat16* __restrict__ Bh, const __nv_bfloat16* __restrict__ Bl,
                    const float* __restrict__ bias, const float* __restrict__ res,
                    float* __restrict__ C, int K, int ldb, int ldc) {
    extern __shared__ char smem[];
    const int tid = threadIdx.x, wid = tid >> 5, lane = tid & 31;
    const int bm = blockIdx.y * 64, bn = blockIdx.x * 64;
    const int wm = (wid >> 1) * 16, wn = (wid & 1) * 32;
    float acc[4][4] = {};
    gemm_core_t64(acc, Ah, Al, Bh, Bl, K, ldb, bm, bn, smem);
    int r0 = bm + wm + (lane >> 2);
#pragma unroll
    for (int nf = 0; nf < 4; nf++) {
        int col = bn + wn + nf * 8 + ((lane & 3) << 1);
        float v0 = acc[nf][0], v1 = acc[nf][1];
        float v2 = acc[nf][2], v3 = acc[nf][3];
        if (bias) {
            float b0 = bias[col], b1 = bias[col + 1];
            v0 += b0; v1 += b1; v2 += b0; v3 += b1;
        }
        if (res) {
            const float* rr0 = res + (size_t)r0 * ldc + col;
            const float* rr1 = res + (size_t)(r0 + 8) * ldc + col;
            v0 += rr0[0]; v1 += rr0[1]; v2 += rr1[0]; v3 += rr1[1];
        }
        *(float2*)(C + (size_t)r0 * ldc + col) = make_float2(v0, v1);
        *(float2*)(C + (size_t)(r0 + 8) * ldc + col) = make_float2(v2, v3);
    }
}

// bf16 hi/lo output (+bias, relu) — FFN1
__global__ __launch_bounds__(256, 2)
void k_gemm_bf16(const __nv_bfloat16* __restrict__ Ah, const __nv_bfloat16* __restrict__ Al,
                 const __nv_bfloat16* __restrict__ Bh, const __nv_bfloat16* __restrict__ Bl,
                 const float* __restrict__ bias,
                 __nv_bfloat16* __restrict__ Ch, __nv_bfloat16* __restrict__ Cl,
                 int K, int ldb, int ldc, int relu) {
    extern __shared__ char smem[];
    const int tid = threadIdx.x, wid = tid >> 5, lane = tid & 31;
    const int bm = blockIdx.y * 128, bn = blockIdx.x * 128;
    const int wm = (wid >> 2) * 64, wn = (wid & 3) * 32;
    float acc[4][4][4] = {};
    gemm_core(acc, Ah, Al, Bh, Bl, K, ldb, bm, bn, smem);
#pragma unroll
    for (int m = 0; m < 4; m++) {
        int r0 = bm + wm + m * 16 + (lane >> 2);
#pragma unroll
        for (int nf = 0; nf < 4; nf++) {
            int col = bn + wn + nf * 8 + ((lane & 3) << 1);
            float v[4] = {acc[m][nf][0], acc[m][nf][1], acc[m][nf][2], acc[m][nf][3]};
            if (bias) {
                float b0 = bias[col], b1 = bias[col + 1];
                v[0] += b0; v[1] += b1; v[2] += b0; v[3] += b1;
            }
            if (relu) {
#pragma unroll
                for (int e = 0; e < 4; e++) v[e] = fmaxf(v[e], 0.f);
            }
            float h0 = __bfloat162float(__float2bfloat16(v[0]));
            float h1 = __bfloat162float(__float2bfloat16(v[1]));
            float h2 = __bfloat162float(__float2bfloat16(v[2]));
            float h3 = __bfloat162float(__float2bfloat16(v[3]));
            *(uint32_t*)(Ch + (size_t)r0 * ldc + col) = pack2bf(v[0], v[1]);
            *(uint32_t*)(Ch + (size_t)(r0 + 8) * ldc + col) = pack2bf(v[2], v[3]);
            *(uint32_t*)(Cl + (size_t)r0 * ldc + col) = pack2bf(v[0] - h0, v[1] - h1);
            *(uint32_t*)(Cl + (size_t)(r0 + 8) * ldc + col) = pack2bf(v[2] - h2, v[3] - h3);
        }
    }
}

// QKV gemm: B = [3][D,D]; cols [0,D)->q, [D,2D)->k, [2D,3D)->vT via smem
__global__ __launch_bounds__(256, 2)
void k_qkv_gemm(const __nv_bfloat16* __restrict__ Ah, const __nv_bfloat16* __restrict__ Al,
                const __nv_bfloat16* __restrict__ Bh, const __nv_bfloat16* __restrict__ Bl,
                __nv_bfloat16* __restrict__ qh, __nv_bfloat16* __restrict__ ql,
                __nv_bfloat16* __restrict__ kh, __nv_bfloat16* __restrict__ kl,
                __nv_bfloat16* __restrict__ vth, __nv_bfloat16* __restrict__ vtl) {
    extern __shared__ char smem[];
    const int tid = threadIdx.x, wid = tid >> 5, lane = tid & 31;
    const int bm = blockIdx.y * 128, bn = blockIdx.x * 128;
    const int wm = (wid >> 2) * 64, wn = (wid & 3) * 32;
    const int widx = bn >> 10;
    const int bn_eff = bn & 1023;
    float acc[4][4][4] = {};
    gemm_core(acc, Ah, Al, Bh + (size_t)widx * D * D, Bl + (size_t)widx * D * D,
              D, D, bm, bn_eff, smem);

    if (widx < 2) {
        __nv_bfloat16* oh = (widx == 0) ? qh : kh;
        __nv_bfloat16* ol = (widx == 0) ? ql : kl;
#pragma unroll
        for (int m = 0; m < 4; m++) {
            int r0 = bm + wm + m * 16 + (lane >> 2);
#pragma unroll
            for (int nf = 0; nf < 4; nf++) {
                int col = bn_eff + wn + nf * 8 + ((lane & 3) << 1);
                float v0 = acc[m][nf][0], v1 = acc[m][nf][1];
                float v2 = acc[m][nf][2], v3 = acc[m][nf][3];
                float h0 = __bfloat162float(__float2bfloat16(v0));
                float h1 = __bfloat162float(__float2bfloat16(v1));
                float h2 = __bfloat162float(__float2bfloat16(v2));
                float h3 = __bfloat162float(__float2bfloat16(v3));
                *(uint32_t*)(oh + (size_t)r0 * D + col) = pack2bf(v0, v1);
                *(uint32_t*)(oh + (size_t)(r0 + 8) * D + col) = pack2bf(v2, v3);
                *(uint32_t*)(ol + (size_t)r0 * D + col) = pack2bf(v0 - h0, v1 - h1);
                *(uint32_t*)(ol + (size_t)(r0 + 8) * D + col) = pack2bf(v2 - h2, v3 - h3);
            }
        }
    } else {
        __syncthreads();
        __nv_bfloat16* sv = (__nv_bfloat16*)smem;
#pragma unroll
        for (int part = 0; part < 2; part++) {
#pragma unroll
            for (int m = 0; m < 4; m++) {
#pragma unroll
                for (int nf = 0; nf < 4; nf++) {
#pragma unroll
                    for (int e = 0; e < 4; e++) {
                        int rl = wm + m * 16 + (lane >> 2) + ((e >> 1) ? 8 : 0);
                        int cl = wn + nf * 8 + ((lane & 3) << 1) + (e & 1);
                        float v = acc[m][nf][e];
                        float hv = __bfloat162float(__float2bfloat16(v));
                        sv[cl * 136 + rl] = __float2bfloat16(part ? (v - hv) : v);
                    }
                }
            }
            __syncthreads();
            int col = tid >> 1, half = tid & 1;
            const uint4* src = (const uint4*)(smem + col * 272 + half * 128);
            __nv_bfloat16* dst = (part ? vtl : vth) +
                                 (size_t)(bn_eff + col) * S + bm + half * 64;
#pragma unroll
            for (int j = 0; j < 8; j++) ((uint4*)dst)[j] = src[j];
            __syncthreads();
        }
    }
}

// ---------------------------------------------------------------------------
// flash attention: CTA = (qblock 64, head), 128 thr
// ---------------------------------------------------------------------------
#define FA_SMEM (16384 + 2 * 32768)

__device__ __forceinline__ void fa_load(uint32_t sdst, const __nv_bfloat16* g,
                                        int ld, int tid) {
#pragma unroll
    for (int i = 0; i < 4; i++) {
        int cid = i * 128 + tid;
        int row = cid >> 3, c = cid & 7;
        CP16(sdst + row * 128 + ((c ^ (row & 7)) << 4), g + (size_t)row * ld + c * 8);
    }
}

__global__ __launch_bounds__(128)
void k_flash(const __nv_bfloat16* __restrict__ qh, const __nv_bfloat16* __restrict__ ql,
             const __nv_bfloat16* __restrict__ kh, const __nv_bfloat16* __restrict__ kl,
             const __nv_bfloat16* __restrict__ vth, const __nv_bfloat16* __restrict__ vtl,
             __nv_bfloat16* __restrict__ oh, __nv_bfloat16* __restrict__ ol) {
    extern __shared__ char smem[];
    uint32_t sb = smem_u32(smem);
    const int tid = threadIdx.x, w = tid >> 5, lane = tid & 31;
    const int qb = gridDim.x - 1 - blockIdx.x;
    const int hh = blockIdx.y;

    fa_load(sb,        qh + (size_t)(qb * 64) * D + hh * 64, D, tid);
    fa_load(sb + 8192, ql + (size_t)(qb * 64) * D + hh * 64, D, tid);
    {
        uint32_t st = sb + 16384;
        fa_load(st,         kh + hh * 64, D, tid);
        fa_load(st + 8192,  kl + hh * 64, D, tid);
        fa_load(st + 16384, vth + (size_t)(hh * 64) * S, S, tid);
        fa_load(st + 24576, vtl + (size_t)(hh * 64) * S, S, tid);
    }
    CP_COMMIT();

    uint32_t qhf[4][4], qlf[4][4];
    float o_acc[8][4] = {};
    float m0 = -1e30f, m1 = -1e30f, l0 = 0.f, l1 = 0.f;

    for (int kb = 0; kb <= qb; kb++) {
        if (kb + 1 <= qb) {
            uint32_t st = sb + 16384 + ((kb + 1) & 1) * 32768;
            fa_load(st,         kh + (size_t)((kb + 1) * 64) * D + hh * 64, D, tid);
            fa_load(st + 8192,  kl + (size_t)((kb + 1) * 64) * D + hh * 64, D, tid);
            fa_load(st + 16384, vth + (size_t)(hh * 64) * S + (kb + 1) * 64, S, tid);
            fa_load(st + 24576, vtl + (size_t)(hh * 64) * S + (kb + 1) * 64, S, tid);
            CP_COMMIT();
            CP_WAIT(1);
        } else {
            CP_WAIT(0);
        }
        __syncthreads();

        if (kb == 0) {
#pragma unroll
            for (int f = 0; f < 4; f++) {
                int row = w * 16 + (lane & 15);
                int jc = (lane >> 4) + f * 2;
                ldsm4(qhf[f], sb + row * 128 + ((jc ^ (row & 7)) << 4));
                ldsm4(qlf[f], sb + 8192 + row * 128 + ((jc ^ (row & 7)) << 4));
            }
        }

        uint32_t st = sb + 16384 + (kb & 1) * 32768;
        float s_acc[8][4] = {};
#pragma unroll
        for (int ks = 0; ks < 4; ks++) {
            uint32_t bh4[4][4], bl4[4][4];
#pragma unroll
            for (int np = 0; np < 4; np++) {
                int row = np * 16 + ((lane >> 4) << 3) + (lane & 7);
                int jc = ((lane >> 3) & 1) + ks * 2;
                ldsm4(bh4[np], st + row * 128 + ((jc ^ (row & 7)) << 4));
                ldsm4(bl4[np], st + 8192 + row * 128 + ((jc ^ (row & 7)) << 4));
            }
#pragma unroll
            for (int nf = 0; nf < 8; nf++) {
                uint32_t* bh = &bh4[nf >> 1][(nf & 1) * 2];
                uint32_t* bl = &bl4[nf >> 1][(nf & 1) * 2];
                mma_bf16(s_acc[nf], qhf[ks], bh);
                mma_bf16(s_acc[nf], qhf[ks], bl);
                mma_bf16(s_acc[nf], qlf[ks], bh);
            }
        }
        int r_lo = qb * 64 + w * 16 + (lane >> 2);
#pragma unroll
        for (int nf = 0; nf < 8; nf++)
#pragma unroll
            for (int e = 0; e < 4; e++) {
                float v = s_acc[nf][e] * 0.125f;
                if (kb == qb) {
                    int key = kb * 64 + nf * 8 + ((lane & 3) << 1) + (e & 1);
                    int qr = r_lo + ((e >> 1) ? 8 : 0);
                    if (key > qr) v = -1e30f;
                }
                s_acc[nf][e] = v;
            }
        float mx0 = -1e30f, mx1 = -1e30f;
#pragma unroll
        for (int nf = 0; nf < 8; nf++) {
            mx0 = fmaxf(mx0, fmaxf(s_acc[nf][0], s_acc[nf][1]));
            mx1 = fmaxf(mx1, fmaxf(s_acc[nf][2], s_acc[nf][3]));
        }
        mx0 = fmaxf(mx0, __shfl_xor_sync(0xffffffffu, mx0, 1));
        mx0 = fmaxf(mx0, __shfl_xor_sync(0xffffffffu, mx0, 2));
        mx1 = fmaxf(mx1, __shfl_xor_sync(0xffffffffu, mx1, 1));
        mx1 = fmaxf(mx1, __shfl_xor_sync(0xffffffffu, mx1, 2));
        float mn0 = fmaxf(m0, mx0), mn1 = fmaxf(m1, mx1);
        float a0 = __expf(m0 - mn0), a1 = __expf(m1 - mn1);
        float sum0 = 0.f, sum1 = 0.f;
#pragma unroll
        for (int nf = 0; nf < 8; nf++) {
            s_acc[nf][0] = __expf(s_acc[nf][0] - mn0);
            s_acc[nf][1] = __expf(s_acc[nf][1] - mn0);
            s_acc[nf][2] = __expf(s_acc[nf][2] - mn1);
            s_acc[nf][3] = __expf(s_acc[nf][3] - mn1);
            sum0 += s_acc[nf][0] + s_acc[nf][1];
            sum1 += s_acc[nf][2] + s_acc[nf][3];
        }
        sum0 += __shfl_xor_sync(0xffffffffu, sum0, 1);
        sum0 += __shfl_xor_sync(0xffffffffu, sum0, 2);
        sum1 += __shfl_xor_sync(0xffffffffu, sum1, 1);
        sum1 += __shfl_xor_sync(0xffffffffu, sum1, 2);
        l0 = l0 * a0 + sum0;
        l1 = l1 * a1 + sum1;
        m0 = mn0; m1 = mn1;
#pragma unroll
        for (int nf = 0; nf < 8; nf++) {
            o_acc[nf][0] *= a0; o_acc[nf][1] *= a0;
            o_acc[nf][2] *= a1; o_acc[nf][3] *= a1;
        }
        uint32_t pph[4][4], ppl[4][4];
#pragma unroll
        for (int g = 0; g < 4; g++) {
            float c0 = s_acc[2 * g][0], c1 = s_acc[2 * g][1];
            float c2 = s_acc[2 * g][2], c3 = s_acc[2 * g][3];
            float d0 = s_acc[2 * g + 1][0], d1 = s_acc[2 * g + 1][1];
            float d2 = s_acc[2 * g + 1][2], d3 = s_acc[2 * g + 1][3];
            pph[g][0] = pack2bf(c0, c1); pph[g][1] = pack2bf(c2, c3);
            pph[g][2] = pack2bf(d0, d1); pph[g][3] = pack2bf(d2, d3);
            ppl[g][0] = pack2bf(c0 - __bfloat162float(__float2bfloat16(c0)),
                                c1 - __bfloat162float(__float2bfloat16(c1)));
            ppl[g][1] = pack2bf(c2 - __bfloat162float(__float2bfloat16(c2)),
                                c3 - __bfloat162float(__float2bfloat16(c3)));
            ppl[g][2] = pack2bf(d0 - __bfloat162float(__float2bfloat16(d0)),
                                d1 - __bfloat162float(__float2bfloat16(d1)));
            ppl[g][3] = pack2bf(d2 - __bfloat162float(__float2bfloat16(d2)),
                                d3 - __bfloat162float(__float2bfloat16(d3)));
        }
        uint32_t sv = st + 16384;
#pragma unroll
        for (int ks = 0; ks < 4; ks++) {
            uint32_t bh4[4][4], bl4[4][4];
#pragma unroll
            for (int np = 0; np < 4; np++) {
                int row = np * 16 + ((lane >> 4) << 3) + (lane & 7);
                int jc = ((lane >> 3) & 1) + ks * 2;
                ldsm4(bh4[np], sv + row * 128 + ((jc ^ (row & 7)) << 4));
                ldsm4(bl4[np], sv + 8192 + row * 128 + ((jc ^ (row & 7)) << 4));
            }
#pragma unroll
            for (int nf = 0; nf < 8; nf++) {
                uint32_t* bh = &bh4[nf >> 1][(nf & 1) * 2];
                uint32_t* bl = &bl4[nf >> 1][(nf & 1) * 2];
                mma_bf16(o_acc[nf], pph[ks], bh);
                mma_bf16(o_acc[nf], ppl[ks], bh);
                mma_bf16(o_acc[nf], pph[ks], bl);
            }
        }
        __syncthreads();
    }

    float inv0 = 1.f / l0, inv1 = 1.f / l1;
    int row0 = qb * 64 + w * 16 + (lane >> 2);
#pragma unroll
    for (int nf = 0; nf < 8; nf++) {
        int col = hh * 64 + nf * 8 + ((lane & 3) << 1);
        float v0 = o_acc[nf][0] * inv0, v1 = o_acc[nf][1] * inv0;
        float v2 = o_acc[nf][2] * inv1, v3 = o_acc[nf][3] * inv1;
        float h0 = __bfloat162float(__float2bfloat16(v0));
        float h1 = __bfloat162float(__float2bfloat16(v1));
        float h2 = __bfloat162float(__float2bfloat16(v2));
        float h3 = __bfloat162float(__float2bfloat16(v3));
        *(uint32_t*)(oh + (size_t)row0 * D + col) = pack2bf(v0, v1);
        *(uint32_t*)(oh + (size_t)(row0 + 8) * D + col) = pack2bf(v2, v3);
        *(uint32_t*)(ol + (size_t)row0 * D + col) = pack2bf(v0 - h0, v1 - h1);
        *(uint32_t*)(ol + (size_t)(row0 + 8) * D + col) = pack2bf(v2 - h2, v3 - h3);
    }
}

// ---------------------------------------------------------------------------
// flat weight split: 16 elems/thread (MLP=4), grid = n/4096
// ---------------------------------------------------------------------------
__global__ __launch_bounds__(256) void k_split_flat(const float* __restrict__ W,
                                                    __nv_bfloat16* __restrict__ th,
                                                    __nv_bfloat16* __restrict__ tl) {
    size_t gid = (size_t)blockIdx.x * 256 + threadIdx.x;
    float4 a[4];
#pragma unroll
    for (int i = 0; i < 4; i++) a[i] = ((const float4*)W)[4 * gid + i];
    uint4 uh[2], ul[2];
#pragma unroll
    for (int i = 0; i < 2; i++) {
        float4 p = a[2 * i], q = a[2 * i + 1];
        uh[i].x = pack2bf(p.x, p.y); uh[i].y = pack2bf(p.z, p.w);
        uh[i].z = pack2bf(q.x, q.y); uh[i].w = pack2bf(q.z, q.w);
        ul[i].x = pack2bf(p.x - __bfloat162float(__float2bfloat16(p.x)),
                          p.y - __bfloat162float(__float2bfloat16(p.y)));
        ul[i].y = pack2bf(p.z - __bfloat162float(__float2bfloat16(p.z)),
                          p.w - __bfloat162float(__float2bfloat16(p.w)));
        ul[i].z = pack2bf(q.x - __bfloat162float(__float2bfloat16(q.x)),
                          q.y - __bfloat162float(__float2bfloat16(q.y)));
        ul[i].w = pack2bf(q.z - __bfloat162float(__float2bfloat16(q.z)),
                          q.w - __bfloat162float(__float2bfloat16(q.w)));
    }
    ((uint4*)th)[2 * gid] = uh[0];
    ((uint4*)th)[2 * gid + 1] = uh[1];
    ((uint4*)tl)[2 * gid] = ul[0];
    ((uint4*)tl)[2 * gid + 1] = ul[1];
}

// ---------------------------------------------------------------------------
// embedding + positional encoding
// ---------------------------------------------------------------------------
__global__ __launch_bounds__(256) void k_embed(const int* __restrict__ x,
                                               const float* __restrict__ emb,
                                               float* __restrict__ h) {
    int s = blockIdx.y;
    int d = blockIdx.x * 256 + threadIdx.x;
    int tok = x[s];
    float e = emb[(size_t)tok * D + d];
    int i2 = d & ~1;
    float freq = expf((float)i2 * (-9.210340371976184f / (float)D));
    float ang = (float)s * freq;
    float pe = (d & 1) ? cosf(ang) : sinf(ang);
    h[(size_t)s * D + d] = e + pe;
}

// ---------------------------------------------------------------------------
// layernorm -> bf16 hi/lo (warp-shuffle reduce, 1 barrier)
// ---------------------------------------------------------------------------
__global__ __launch_bounds__(256) void k_ln(const float* __restrict__ in,
                                            __nv_bfloat16* __restrict__ oh,
                                            __nv_bfloat16* __restrict__ ol,
                                            const float* __restrict__ w,
                                            const float* __restrict__ b) {
    int row = blockIdx.x;
    const float* xr = in + (size_t)row * D;
    int t = threadIdx.x, wid = t >> 5, lane = t & 31;
    __shared__ float w1s[8], w2s[8];
    float s1 = 0.f, s2 = 0.f;
    for (int d = t; d < D; d += 256) {
        float v = xr[d];
        s1 += v; s2 += v * v;
    }
#pragma unroll
    for (int o = 16; o > 0; o >>= 1) {
        s1 += __shfl_xor_sync(0xffffffffu, s1, o);
        s2 += __shfl_xor_sync(0xffffffffu, s2, o);
    }
    if (lane == 0) { w1s[wid] = s1; w2s[wid] = s2; }
    __syncthreads();
    float t1 = 0.f, t2 = 0.f;
#pragma unroll
    for (int i = 0; i < 8; i++) { t1 += w1s[i]; t2 += w2s[i]; }
    float mean = t1 * (1.0f / D);
    float var = t2 * (1.0f / D) - mean * mean;
    float rstd = rsqrtf(var + EPSF);
    for (int d = t; d < D; d += 256) {
        float v = (xr[d] - mean) * rstd * w[d] + b[d];
        __nv_bfloat16 hv = __float2bfloat16(v);
        oh[(size_t)row * D + d] = hv;
        ol[(size_t)row * D + d] = __float2bfloat16(v - __bfloat162float(hv));
    }
}

// ---------------------------------------------------------------------------
// launch orchestration (two streams: s1 compute, s2 weight prep)
// ---------------------------------------------------------------------------
extern "C" void kernel_launch(void* const* d_in, const int* in_sizes, int n_in,
                              void* d_out, int out_size) {
    (void)in_sizes; (void)n_in; (void)out_size;
    const int*   x      = (const int*)d_in[0];
    const float* emb    = (const float*)d_in[1];
    const float* Wq     = (const float*)d_in[2];
    const float* Wk     = (const float*)d_in[3];
    const float* Wv     = (const float*)d_in[4];
    const float* Wo     = (const float*)d_in[5];
    const float* bo     = (const float*)d_in[6];
    const float* ln1_w  = (const float*)d_in[7];
    const float* ln1_b  = (const float*)d_in[8];
    const float* W1     = (const float*)d_in[9];
    const float* b1     = (const float*)d_in[10];
    const float* W2     = (const float*)d_in[11];
    const float* b2     = (const float*)d_in[12];
    const float* ln2_w  = (const float*)d_in[13];
    const float* ln2_b  = (const float*)d_in[14];
    const float* fn_w   = (const float*)d_in[15];
    const float* fn_b   = (const float*)d_in[16];
    const float* lmhead = (const float*)d_in[17];
    float* out = (float*)d_out;

    static float* ph = nullptr;
    static __nv_bfloat16 *acth, *actl, *ffh, *ffl, *qh, *ql, *kh, *kl, *vth, *vtl,
                         *qkvh, *qkvl, *woh, *wol, *w1h, *w1l, *w2h, *w2l, *lmh, *lml;
    static cudaStream_t s1, s2;
    static cudaEvent_t evFork, evW[L], evLM, evDone;
    if (!ph) {
        cudaGetSymbolAddress((void**)&ph,   g_h);
        cudaGetSymbolAddress((void**)&acth, g_act_h);
        cudaGetSymbolAddress((void**)&actl, g_act_l);
        cudaGetSymbolAddress((void**)&ffh,  g_ff_h);
        cudaGetSymbolAddress((void**)&ffl,  g_ff_l);
        cudaGetSymbolAddress((void**)&qh,   g_qh);
        cudaGetSymbolAddress((void**)&ql,   g_ql);
        cudaGetSymbolAddress((void**)&kh,   g_kh);
        cudaGetSymbolAddress((void**)&kl,   g_kl);
        cudaGetSymbolAddress((void**)&vth,  g_vth);
        cudaGetSymbolAddress((void**)&vtl,  g_vtl);
        cudaGetSymbolAddress((void**)&qkvh, g_qkv_h);
        cudaGetSymbolAddress((void**)&qkvl, g_qkv_l);
        cudaGetSymbolAddress((void**)&woh,  g_wo_h);
        cudaGetSymbolAddress((void**)&wol,  g_wo_l);
        cudaGetSymbolAddress((void**)&w1h,  g_w1_h);
        cudaGetSymbolAddress((void**)&w1l,  g_w1_l);
        cudaGetSymbolAddress((void**)&w2h,  g_w2_h);
        cudaGetSymbolAddress((void**)&w2l,  g_w2_l);
        cudaGetSymbolAddress((void**)&lmh,  g_lm_h);
        cudaGetSymbolAddress((void**)&lml,  g_lm_l);
        cudaFuncSetAttribute(k_gemm_f32,     cudaFuncAttributeMaxDynamicSharedMemorySize, MG_SMEM);
        cudaFuncSetAttribute(k_gemm_f32_t64, cudaFuncAttributeMaxDynamicSharedMemorySize, T64_SMEM);
        cudaFuncSetAttribute(k_gemm_bf16,    cudaFuncAttributeMaxDynamicSharedMemorySize, MG_SMEM);
        cudaFuncSetAttribute(k_qkv_gemm,     cudaFuncAttributeMaxDynamicSharedMemorySize, MG_SMEM);
        cudaFuncSetAttribute(k_flash,        cudaFuncAttributeMaxDynamicSharedMemorySize, FA_SMEM);
        cudaStreamCreateWithFlags(&s1, cudaStreamNonBlocking);
        cudaStreamCreateWithFlags(&s2, cudaStreamNonBlocking);
        cudaEventCreateWithFlags(&evFork, cudaEventDisableTiming);
        for (int l = 0; l < L; l++) cudaEventCreateWithFlags(&evW[l], cudaEventDisableTiming);
        cudaEventCreateWithFlags(&evLM, cudaEventDisableTiming);
        cudaEventCreateWithFlags(&evDone, cudaEventDisableTiming);
    }

    // fork
    cudaEventRecord(evFork, 0);
    cudaStreamWaitEvent(s1, evFork, 0);
    cudaStreamWaitEvent(s2, evFork, 0);

    // s2: weight prep (16 elts/thread; grid = n/4096)
    const int gDD = D * D / 4096;       // 256
    const int gDF = D * FF / 4096;      // 1024
    for (int l = 0; l < L; l++) {
        size_t wo = (size_t)l * D * D;
        size_t qo = (size_t)l * 3 * D * D;
        k_split_flat<<<gDD, 256, 0, s2>>>(Wq + wo, qkvh + qo,             qkvl + qo);
        k_split_flat<<<gDD, 256, 0, s2>>>(Wk + wo, qkvh + qo + D * D,     qkvl + qo + D * D);
        k_split_flat<<<gDD, 256, 0, s2>>>(Wv + wo, qkvh + qo + 2 * D * D, qkvl + qo + 2 * D * D);
        k_split_flat<<<gDD, 256, 0, s2>>>(Wo + wo, woh + wo, wol + wo);
        k_split_flat<<<gDF, 256, 0, s2>>>(W1 + (size_t)l * D * FF,
                                          w1h + (size_t)l * D * FF, w1l + (size_t)l * D * FF);
        k_split_flat<<<gDF, 256, 0, s2>>>(W2 + (size_t)l * FF * D,
                                          w2h + (size_t)l * FF * D, w2l + (size_t)l * FF * D);
        cudaEventRecord(evW[l], s2);
    }
    k_split_flat<<<(int)((size_t)D * V / 4096), 256, 0, s2>>>(lmhead, lmh, lml);
    cudaEventRecord(evLM, s2);

    // s1: compute
    k_embed<<<dim3(D / 256, S), 256, 0, s1>>>(x, emb, ph);

    for (int l = 0; l < L; l++) {
        size_t wo = (size_t)l * D * D;
        size_t qo = (size_t)l * 3 * D * D;
        cudaStreamWaitEvent(s1, evW[l], 0);
        // --- attention ---
        k_ln<<<S, 256, 0, s1>>>(ph, acth, actl, ln1_w + (size_t)l * D, ln1_b + (size_t)l * D);
        k_qkv_gemm<<<dim3(3 * D / 128, S / 128), 256, MG_SMEM, s1>>>(
            acth, actl, qkvh + qo, qkvl + qo, qh, ql, kh, kl, vth, vtl);
        k_flash<<<dim3(S / 64, H), 128, FA_SMEM, s1>>>(qh, ql, kh, kl, vth, vtl, acth, actl);
        k_gemm_f32_t64<<<dim3(D / 64, S / 64), 256, T64_SMEM, s1>>>(
            acth, actl, woh + wo, wol + wo, bo + (size_t)l * D, ph, ph, D, D, D);
        // --- FFN ---
        k_ln<<<S, 256, 0, s1>>>(ph, acth, actl, ln2_w + (size_t)l * D, ln2_b + (size_t)l * D);
        k_gemm_bf16<<<dim3(FF / 128, S / 128), 256, MG_SMEM, s1>>>(
            acth, actl, w1h + (size_t)l * D * FF, w1l + (size_t)l * D * FF,
            b1 + (size_t)l * FF, ffh, ffl, D, FF, FF, 1);
        k_gemm_f32_t64<<<dim3(D / 64, S / 64), 256, T64_SMEM, s1>>>(
            ffh, ffl, w2h + (size_t)l * FF * D, w2l + (size_t)l * FF * D,
            b2 + (size_t)l * D, ph, ph, FF, D, D);
    }

    // final LN + LM head
    cudaStreamWaitEvent(s1, evLM, 0);
    k_ln<<<S, 256, 0, s1>>>(ph, acth, actl, fn_w, fn_b);
    k_gemm_f32<<<dim3(V / 128, S / 128), 256, MG_SMEM, s1>>>(
        acth, actl, lmh, lml, nullptr, nullptr, out, D, V, V);

    // join
    cudaEventRecord(evDone, s1);
    cudaStreamWaitEvent(0, evDone, 0);
}

// round 12
// speedup vs baseline: 1.0128x; 1.0128x over previous
#include <cuda_runtime.h>
#include <cuda_bf16.h>
#include <math.h>
#include <stdint.h>

#define S 1024
#define D 1024
#define H 16
#define HD 64
#define L 4
#define FF 4096
#define V 32000
#define EPSF 1e-5f

// ---------------------------------------------------------------------------
// device scratch
// ---------------------------------------------------------------------------
__device__ __align__(16) float g_h[S * D];

__device__ __align__(16) __nv_bfloat16 g_act_h[S * FF];
__device__ __align__(16) __nv_bfloat16 g_act_l[S * FF];
__device__ __align__(16) __nv_bfloat16 g_ff_h[S * FF];
__device__ __align__(16) __nv_bfloat16 g_ff_l[S * FF];
__device__ __align__(16) __nv_bfloat16 g_qh[S * D];
__device__ __align__(16) __nv_bfloat16 g_ql[S * D];
__device__ __align__(16) __nv_bfloat16 g_kh[S * D];
__device__ __align__(16) __nv_bfloat16 g_kl[S * D];
__device__ __align__(16) __nv_bfloat16 g_vth[D * S];
__device__ __align__(16) __nv_bfloat16 g_vtl[D * S];

// weights: K-major [K,N] bf16 hi/lo
__device__ __align__(16) __nv_bfloat16 g_qkv_h[(size_t)L * 3 * D * D];
__device__ __align__(16) __nv_bfloat16 g_qkv_l[(size_t)L * 3 * D * D];
__device__ __align__(16) __nv_bfloat16 g_wo_h[(size_t)L * D * D];
__device__ __align__(16) __nv_bfloat16 g_wo_l[(size_t)L * D * D];
__device__ __align__(16) __nv_bfloat16 g_w1_h[(size_t)L * D * FF];
__device__ __align__(16) __nv_bfloat16 g_w1_l[(size_t)L * D * FF];
__device__ __align__(16) __nv_bfloat16 g_w2_h[(size_t)L * FF * D];
__device__ __align__(16) __nv_bfloat16 g_w2_l[(size_t)L * FF * D];
__device__ __align__(16) __nv_bfloat16 g_lm_h[(size_t)D * V];
__device__ __align__(16) __nv_bfloat16 g_lm_l[(size_t)D * V];

// ---------------------------------------------------------------------------
// PTX helpers
// ---------------------------------------------------------------------------
__device__ __forceinline__ uint32_t smem_u32(const void* p) {
    uint32_t a;
    asm("{ .reg .u64 t; cvta.to.shared.u64 t, %1; cvt.u32.u64 %0, t; }" : "=r"(a) : "l"(p));
    return a;
}
#define CP16(dst, src) \
    asm volatile("cp.async.cg.shared.global [%0], [%1], 16;" :: "r"(dst), "l"(src))
#define CP_COMMIT() asm volatile("cp.async.commit_group;" ::: "memory")
#define CP_WAIT(n)  asm volatile("cp.async.wait_group %0;" :: "n"(n) : "memory")

__device__ __forceinline__ void ldsm4(uint32_t* r, uint32_t addr) {
    asm volatile("ldmatrix.sync.aligned.m8n8.x4.shared.b16 {%0,%1,%2,%3}, [%4];"
                 : "=r"(r[0]), "=r"(r[1]), "=r"(r[2]), "=r"(r[3]) : "r"(addr));
}
__device__ __forceinline__ void ldsm4t(uint32_t* r, uint32_t addr) {
    asm volatile("ldmatrix.sync.aligned.m8n8.x4.trans.shared.b16 {%0,%1,%2,%3}, [%4];"
                 : "=r"(r[0]), "=r"(r[1]), "=r"(r[2]), "=r"(r[3]) : "r"(addr));
}
__device__ __forceinline__ void mma_bf16(float* d, const uint32_t* a, const uint32_t* b) {
    asm volatile(
        "mma.sync.aligned.m16n8k16.row.col.f32.bf16.bf16.f32 "
        "{%0,%1,%2,%3}, {%4,%5,%6,%7}, {%8,%9}, {%0,%1,%2,%3};"
        : "+f"(d[0]), "+f"(d[1]), "+f"(d[2]), "+f"(d[3])
        : "r"(a[0]), "r"(a[1]), "r"(a[2]), "r"(a[3]), "r"(b[0]), "r"(b[1]));
}
__device__ __forceinline__ uint32_t pack2bf(float a, float b) {
    unsigned short ra = __bfloat16_as_ushort(__float2bfloat16(a));
    unsigned short rb = __bfloat16_as_ushort(__float2bfloat16(b));
    return (uint32_t)ra | ((uint32_t)rb << 16);
}

// ---------------------------------------------------------------------------
// GEMM cores. A row-major hi/lo [M,K]; B K-major hi/lo [K,N]. 3-stage pipe.
// ---------------------------------------------------------------------------
#define MG_SMEM (3 * 32768)
#define T64_SMEM (3 * 16384)

__device__ __forceinline__ void tile_load_A(uint32_t sdst,
                                            const __nv_bfloat16* gh,
                                            const __nv_bfloat16* gl,
                                            int ld, int k0, int tid) {
#pragma unroll
    for (int i = 0; i < 4; i++) {
        int cid = i * 256 + tid;
        int row = cid >> 3, sub = cid & 7;
        const __nv_bfloat16* src =
            ((sub & 4) ? gl : gh) + (size_t)row * ld + k0 + (sub & 3) * 8;
        uint32_t dst = sdst + row * 128 + ((sub ^ (row & 7)) << 4);
        CP16(dst, src);
    }
}

__device__ __forceinline__ void tile_load_A64(uint32_t sdst,
                                              const __nv_bfloat16* gh,
                                              const __nv_bfloat16* gl,
                                              int ld, int k0, int tid) {
#pragma unroll
    for (int i = 0; i < 2; i++) {
        int cid = i * 256 + tid;
        int row = cid >> 3, sub = cid & 7;
        const __nv_bfloat16* src =
            ((sub & 4) ? gl : gh) + (size_t)row * ld + k0 + (sub & 3) * 8;
        uint32_t dst = sdst + row * 128 + ((sub ^ (row & 7)) << 4);
        CP16(dst, src);
    }
}

__device__ __forceinline__ void tile_load_B(uint32_t sdst,
                                            const __nv_bfloat16* gh,
                                            const __nv_bfloat16* gl,
                                            int ldb, int bn, int k0, int tid) {
#pragma unroll
    for (int i = 0; i < 4; i++) {
        int cid = i * 256 + tid;
        int half = cid >> 9;
        int rem = cid & 511;
        int row = rem >> 4, c = rem & 15;
        const __nv_bfloat16* src =
            (half ? gl : gh) + (size_t)(k0 + row) * ldb + bn + c * 8;
        uint32_t dst = sdst + half * 8192 + row * 256 +
                       ((c ^ ((row & 7) << 1)) << 4);
        CP16(dst, src);
    }
}

__device__ __forceinline__ void tile_load_B64(uint32_t sdst,
                                              const __nv_bfloat16* gh,
                                              const __nv_bfloat16* gl,
                                              int ldb, int bn, int k0, int tid) {
#pragma unroll
    for (int i = 0; i < 2; i++) {
        int cid = i * 256 + tid;
        int half = cid >> 8;
        int rem = cid & 255;
        int row = rem >> 3, c = rem & 7;
        const __nv_bfloat16* src =
            (half ? gl : gh) + (size_t)(k0 + row) * ldb + bn + c * 8;
        uint32_t dst = sdst + half * 4096 + row * 128 + ((c ^ (row & 7)) << 4);
        CP16(dst, src);
    }
}

__device__ __forceinline__ void gemm_core(float (&acc)[4][4][4],
                                          const __nv_bfloat16* Ah, const __nv_bfloat16* Al,
                                          const __nv_bfloat16* Bh, const __nv_bfloat16* Bl,
                                          int K, int ldb, int bm, int bn, char* smem) {
    const int tid = threadIdx.x;
    const int wid = tid >> 5, lane = tid & 31;
    const int wm = (wid >> 2) * 64, wn = (wid & 3) * 32;
    uint32_t sbase = smem_u32(smem);

    const __nv_bfloat16* ah_g = Ah + (size_t)bm * K;
    const __nv_bfloat16* al_g = Al + (size_t)bm * K;

    const int nt = K >> 5;
    tile_load_A(sbase, ah_g, al_g, K, 0, tid);
    tile_load_B(sbase + 16384, Bh, Bl, ldb, bn, 0, tid);
    CP_COMMIT();
    tile_load_A(sbase + 32768, ah_g, al_g, K, 32, tid);
    tile_load_B(sbase + 32768 + 16384, Bh, Bl, ldb, bn, 32, tid);
    CP_COMMIT();

    const int kr_base = (lane & 7) + ((lane >> 3) & 1) * 8;
    const int nc8 = (lane >> 4);

    int br = 0, bw = 2;
    for (int t = 0; t < nt; t++) {
        if (t + 1 < nt) { CP_WAIT(1); } else { CP_WAIT(0); }
        __syncthreads();
        if (t + 2 < nt) {
            uint32_t nb = sbase + bw * 32768;
            tile_load_A(nb, ah_g, al_g, K, (t + 2) << 5, tid);
            tile_load_B(nb + 16384, Bh, Bl, ldb, bn, (t + 2) << 5, tid);
            CP_COMMIT();
        }

        uint32_t sA = sbase + br * 32768;
        uint32_t sB = sA + 16384;
#pragma unroll
        for (int ks = 0; ks < 2; ks++) {
            uint32_t bhf[2][4], blf[2][4];
#pragma unroll
            for (int np = 0; np < 2; np++) {
                int krow = ks * 16 + kr_base;
                int ncol = wn + np * 16 + nc8 * 8;
                int c = ncol >> 3;
                uint32_t a = sB + krow * 256 + ((c ^ ((krow & 7) << 1)) << 4);
                ldsm4t(bhf[np], a);
                ldsm4t(blf[np], a + 8192);
            }
#pragma unroll
            for (int mp = 0; mp < 2; mp++) {
                uint32_t ahf[2][4], alf[2][4];
#pragma unroll
                for (int f2 = 0; f2 < 2; f2++) {
                    int row = wm + (mp * 2 + f2) * 16 + (lane & 15);
                    int jc = (lane >> 4) + ks * 2;
                    ldsm4(ahf[f2], sA + row * 128 + ((jc ^ (row & 7)) << 4));
                    ldsm4(alf[f2], sA + row * 128 + (((jc + 4) ^ (row & 7)) << 4));
                }
#pragma unroll
                for (int m2 = 0; m2 < 2; m2++)
#pragma unroll
                    for (int nf = 0; nf < 4; nf++) {
                        uint32_t* bhp = &bhf[nf >> 1][(nf & 1) * 2];
                        uint32_t* blp = &blf[nf >> 1][(nf & 1) * 2];
                        float* ac = acc[mp * 2 + m2][nf];
                        mma_bf16(ac, ahf[m2], bhp);
                        mma_bf16(ac, ahf[m2], blp);
                        mma_bf16(ac, alf[m2], bhp);
                    }
            }
        }
        br = (br == 2) ? 0 : br + 1;
        bw = (bw == 2) ? 0 : bw + 1;
    }
}

__device__ __forceinline__ void gemm_core_t64(float (&acc)[4][4],
                                              const __nv_bfloat16* Ah, const __nv_bfloat16* Al,
                                              const __nv_bfloat16* Bh, const __nv_bfloat16* Bl,
                                              int K, int ldb, int bm, int bn, char* smem) {
    const int tid = threadIdx.x;
    const int wid = tid >> 5, lane = tid & 31;
    const int wm = (wid >> 1) * 16, wn = (wid & 1) * 32;
    uint32_t sbase = smem_u32(smem);

    const __nv_bfloat16* ah_g = Ah + (size_t)bm * K;
    const __nv_bfloat16* al_g = Al + (size_t)bm * K;

    const int nt = K >> 5;
    tile_load_A64(sbase, ah_g, al_g, K, 0, tid);
    tile_load_B64(sbase + 8192, Bh, Bl, ldb, bn, 0, tid);
    CP_COMMIT();
    tile_load_A64(sbase + 16384, ah_g, al_g, K, 32, tid);
    tile_load_B64(sbase + 16384 + 8192, Bh, Bl, ldb, bn, 32, tid);
    CP_COMMIT();

    const int kr_base = (lane & 7) + ((lane >> 3) & 1) * 8;
    const int nc8 = (lane >> 4);

    int br = 0, bw = 2;
    for (int t = 0; t < nt; t++) {
        if (t + 1 < nt) { CP_WAIT(1); } else { CP_WAIT(0); }
        __syncthreads();
        if (t + 2 < nt) {
            uint32_t nb = sbase + bw * 16384;
            tile_load_A64(nb, ah_g, al_g, K, (t + 2) << 5, tid);
            tile_load_B64(nb + 8192, Bh, Bl, ldb, bn, (t + 2) << 5, tid);
            CP_COMMIT();
        }

        uint32_t sA = sbase + br * 16384;
        uint32_t sB = sA + 8192;
#pragma unroll
        for (int ks = 0; ks < 2; ks++) {
            uint32_t bhf[2][4], blf[2][4];
#pragma unroll
            for (int np = 0; np < 2; np++) {
                int krow = ks * 16 + kr_base;
                int ncol = wn + np * 16 + nc8 * 8;
                int c = ncol >> 3;
                uint32_t a = sB + krow * 128 + ((c ^ (krow & 7)) << 4);
                ldsm4t(bhf[np], a);
                ldsm4t(blf[np], a + 4096);
            }
            uint32_t ahf[4], alf[4];
            {
                int row = wm + (lane & 15);
                int jc = (lane >> 4) + ks * 2;
                ldsm4(ahf, sA + row * 128 + ((jc ^ (row & 7)) << 4));
                ldsm4(alf, sA + row * 128 + (((jc + 4) ^ (row & 7)) << 4));
            }
#pragma unroll
            for (int nf = 0; nf < 4; nf++) {
                uint32_t* bhp = &bhf[nf >> 1][(nf & 1) * 2];
                uint32_t* blp = &blf[nf >> 1][(nf & 1) * 2];
                float* ac = acc[nf];
                mma_bf16(ac, ahf, bhp);
                mma_bf16(ac, ahf, blp);
                mma_bf16(ac, alf, bhp);
            }
        }
        br = (br == 2) ? 0 : br + 1;
        bw = (bw == 2) ? 0 : bw + 1;
    }
}

// fp32 output (+bias, +res), 128-wide N
__global__ __launch_bounds__(256, 2)
void k_gemm_f32(const __nv_bfloat16* __restrict__ Ah, const __nv_bfloat16* __restrict__ Al,
                const __nv_bfloat16* __restrict__ Bh, const __nv_bfloat16* __restrict__ Bl,
                const float* __restrict__ bias, const float* __restrict__ res,
                float* __restrict__ C, int K, int ldb, int ldc) {
    extern __shared__ char smem[];
    const int tid = threadIdx.x, wid = tid >> 5, lane = tid & 31;
    const int bm = blockIdx.y * 128, bn = blockIdx.x * 128;
    const int wm = (wid >> 2) * 64, wn = (wid & 3) * 32;
    float acc[4][4][4] = {};
    gemm_core(acc, Ah, Al, Bh, Bl, K, ldb, bm, bn, smem);
#pragma unroll
    for (int m = 0; m < 4; m++) {
        int r0 = bm + wm + m * 16 + (lane >> 2);
#pragma unroll
        for (int nf = 0; nf < 4; nf++) {
            int col = bn + wn + nf * 8 + ((lane & 3) << 1);
            float v0 = acc[m][nf][0], v1 = acc[m][nf][1];
            float v2 = acc[m][nf][2], v3 = acc[m][nf][3];
            if (bias) {
                float b0 = bias[col], b1 = bias[col + 1];
                v0 += b0; v1 += b1; v2 += b0; v3 += b1;
            }
            if (res) {
                const float* rr0 = res + (size_t)r0 * ldc + col;
                const float* rr1 = res + (size_t)(r0 + 8) * ldc + col;
                v0 += rr0[0]; v1 += rr0[1]; v2 += rr1[0]; v3 += rr1[1];
            }
            *(float2*)(C + (size_t)r0 * ldc + col) = make_float2(v0, v1);
            *(float2*)(C + (size_t)(r0 + 8) * ldc + col) = make_float2(v2, v3);
        }
    }
}

// fp32 output (+bias, +res), 64x64 tile — Wo / FFN2
__global__ __launch_bounds__(256, 2)
void k_gemm_f32_t64(const __nv_bfloat16* __restrict__ Ah, const __nv_bfloat16* __restrict__ Al,
                    const __nv_bfloat16* __restrict__ Bh, const __nv_bfloat16* __restrict__ Bl,
                    const float* __restrict__ bias, const float* __restrict__ res,
                    float* __restrict__ C, int K, int ldb, int ldc) {
    extern __shared__ char smem[];
    const int tid = threadIdx.x, wid = tid >> 5, lane = tid & 31;
    const int bm = blockIdx.y * 64, bn = blockIdx.x * 64;
    const int wm = (wid >> 1) * 16, wn = (wid & 1) * 32;
    float acc[4][4] = {};
    gemm_core_t64(acc, Ah, Al, Bh, Bl, K, ldb, bm, bn, smem);
    int r0 = bm + wm + (lane >> 2);
#pragma unroll
    for (int nf = 0; nf < 4; nf++) {
        int col = bn + wn + nf * 8 + ((lane & 3) << 1);
        float v0 = acc[nf][0], v1 = acc[nf][1];
        float v2 = acc[nf][2], v3 = acc[nf][3];
        if (bias) {
            float b0 = bias[col], b1 = bias[col + 1];
            v0 += b0; v1 += b1; v2 += b0; v3 += b1;
        }
        if (res) {
            const float* rr0 = res + (size_t)r0 * ldc + col;
            const float* rr1 = res + (size_t)(r0 + 8) * ldc + col;
            v0 += rr0[0]; v1 += rr0[1]; v2 += rr1[0]; v3 += rr1[1];
        }
        *(float2*)(C + (size_t)r0 * ldc + col) = make_float2(v0, v1);
        *(float2*)(C + (size_t)(r0 + 8) * ldc + col) = make_float2(v2, v3);
    }
}

// bf16 hi/lo output (+bias, relu) — FFN1
__global__ __launch_bounds__(256, 2)
void k_gemm_bf16(const __nv_bfloat16* __restrict__ Ah, const __nv_bfloat16* __restrict__ Al,
                 const __nv_bfloat16* __restrict__ Bh, const __nv_bfloat16* __restrict__ Bl,
                 const float* __restrict__ bias,
                 __nv_bfloat16* __restrict__ Ch, __nv_bfloat16* __restrict__ Cl,
                 int K, int ldb, int ldc, int relu) {
    extern __shared__ char smem[];
    const int tid = threadIdx.x, wid = tid >> 5, lane = tid & 31;
    const int bm = blockIdx.y * 128, bn = blockIdx.x * 128;
    const int wm = (wid >> 2) * 64, wn = (wid & 3) * 32;
    float acc[4][4][4] = {};
    gemm_core(acc, Ah, Al, Bh, Bl, K, ldb, bm, bn, smem);
#pragma unroll
    for (int m = 0; m < 4; m++) {
        int r0 = bm + wm + m * 16 + (lane >> 2);
#pragma unroll
        for (int nf = 0; nf < 4; nf++) {
            int col = bn + wn + nf * 8 + ((lane & 3) << 1);
            float v[4] = {acc[m][nf][0], acc[m][nf][1], acc[m][nf][2], acc[m][nf][3]};
            if (bias) {
                float b0 = bias[col], b1 = bias[col + 1];
                v[0] += b0; v[1] += b1; v[2] += b0; v[3] += b1;
            }
            if (relu) {
#pragma unroll
                for (int e = 0; e < 4; e++) v[e] = fmaxf(v[e], 0.f);
            }
            float h0 = __bfloat162float(__float2bfloat16(v[0]));
            float h1 = __bfloat162float(__float2bfloat16(v[1]));
            float h2 = __bfloat162float(__float2bfloat16(v[2]));
            float h3 = __bfloat162float(__float2bfloat16(v[3]));
            *(uint32_t*)(Ch + (size_t)r0 * ldc + col) = pack2bf(v[0], v[1]);
            *(uint32_t*)(Ch + (size_t)(r0 + 8) * ldc + col) = pack2bf(v[2], v[3]);
            *(uint32_t*)(Cl + (size_t)r0 * ldc + col) = pack2bf(v[0] - h0, v[1] - h1);
            *(uint32_t*)(Cl + (size_t)(r0 + 8) * ldc + col) = pack2bf(v[2] - h2, v[3] - h3);
        }
    }
}

// QKV gemm: B = [3][D,D]; cols [0,D)->q, [D,2D)->k, [2D,3D)->vT via smem
__global__ __launch_bounds__(256, 2)
void k_qkv_gemm(const __nv_bfloat16* __restrict__ Ah, const __nv_bfloat16* __restrict__ Al,
                const __nv_bfloat16* __restrict__ Bh, const __nv_bfloat16* __restrict__ Bl,
                __nv_bfloat16* __restrict__ qh, __nv_bfloat16* __restrict__ ql,
                __nv_bfloat16* __restrict__ kh, __nv_bfloat16* __restrict__ kl,
                __nv_bfloat16* __restrict__ vth, __nv_bfloat16* __restrict__ vtl) {
    extern __shared__ char smem[];
    const int tid = threadIdx.x, wid = tid >> 5, lane = tid & 31;
    const int bm = blockIdx.y * 128, bn = blockIdx.x * 128;
    const int wm = (wid >> 2) * 64, wn = (wid & 3) * 32;
    const int widx = bn >> 10;
    const int bn_eff = bn & 1023;
    float acc[4][4][4] = {};
    gemm_core(acc, Ah, Al, Bh + (size_t)widx * D * D, Bl + (size_t)widx * D * D,
              D, D, bm, bn_eff, smem);

    if (widx < 2) {
        __nv_bfloat16* oh = (widx == 0) ? qh : kh;
        __nv_bfloat16* ol = (widx == 0) ? ql : kl;
#pragma unroll
        for (int m = 0; m < 4; m++) {
            int r0 = bm + wm + m * 16 + (lane >> 2);
#pragma unroll
            for (int nf = 0; nf < 4; nf++) {
                int col = bn_eff + wn + nf * 8 + ((lane & 3) << 1);
                float v0 = acc[m][nf][0], v1 = acc[m][nf][1];
                float v2 = acc[m][nf][2], v3 = acc[m][nf][3];
                float h0 = __bfloat162float(__float2bfloat16(v0));
                float h1 = __bfloat162float(__float2bfloat16(v1));
                float h2 = __bfloat162float(__float2bfloat16(v2));
                float h3 = __bfloat162float(__float2bfloat16(v3));
                *(uint32_t*)(oh + (size_t)r0 * D + col) = pack2bf(v0, v1);
                *(uint32_t*)(oh + (size_t)(r0 + 8) * D + col) = pack2bf(v2, v3);
                *(uint32_t*)(ol + (size_t)r0 * D + col) = pack2bf(v0 - h0, v1 - h1);
                *(uint32_t*)(ol + (size_t)(r0 + 8) * D + col) = pack2bf(v2 - h2, v3 - h3);
            }
        }
    } else {
        __syncthreads();
        __nv_bfloat16* sv = (__nv_bfloat16*)smem;
#pragma unroll
        for (int part = 0; part < 2; part++) {
#pragma unroll
            for (int m = 0; m < 4; m++) {
#pragma unroll
                for (int nf = 0; nf < 4; nf++) {
#pragma unroll
                    for (int e = 0; e < 4; e++) {
                        int rl = wm + m * 16 + (lane >> 2) + ((e >> 1) ? 8 : 0);
                        int cl = wn + nf * 8 + ((lane & 3) << 1) + (e & 1);
                        float v = acc[m][nf][e];
                        float hv = __bfloat162float(__float2bfloat16(v));
                        sv[cl * 136 + rl] = __float2bfloat16(part ? (v - hv) : v);
                    }
                }
            }
            __syncthreads();
            int col = tid >> 1, half = tid & 1;
            const uint4* src = (const uint4*)(smem + col * 272 + half * 128);
            __nv_bfloat16* dst = (part ? vtl : vth) +
                                 (size_t)(bn_eff + col) * S + bm + half * 64;
#pragma unroll
            for (int j = 0; j < 8; j++) ((uint4*)dst)[j] = src[j];
            __syncthreads();
        }
    }
}

// ---------------------------------------------------------------------------
// flash attention: CTA = (qblock 64, head), 128 thr
// ---------------------------------------------------------------------------
#define FA_SMEM (16384 + 2 * 32768)

__device__ __forceinline__ void fa_load(uint32_t sdst, const __nv_bfloat16* g,
                                        int ld, int tid) {
#pragma unroll
    for (int i = 0; i < 4; i++) {
        int cid = i * 128 + tid;
        int row = cid >> 3, c = cid & 7;
        CP16(sdst + row * 128 + ((c ^ (row & 7)) << 4), g + (size_t)row * ld + c * 8);
    }
}

__global__ __launch_bounds__(128)
void k_flash(const __nv_bfloat16* __restrict__ qh, const __nv_bfloat16* __restrict__ ql,
             const __nv_bfloat16* __restrict__ kh, const __nv_bfloat16* __restrict__ kl,
             const __nv_bfloat16* __restrict__ vth, const __nv_bfloat16* __restrict__ vtl,
             __nv_bfloat16* __restrict__ oh, __nv_bfloat16* __restrict__ ol) {
    extern __shared__ char smem[];
    uint32_t sb = smem_u32(smem);
    const int tid = threadIdx.x, w = tid >> 5, lane = tid & 31;
    const int qb = gridDim.x - 1 - blockIdx.x;
    const int hh = blockIdx.y;

    fa_load(sb,        qh + (size_t)(qb * 64) * D + hh * 64, D, tid);
    fa_load(sb + 8192, ql + (size_t)(qb * 64) * D + hh * 64, D, tid);
    {
        uint32_t st = sb + 16384;
        fa_load(st,         kh + hh * 64, D, tid);
        fa_load(st + 8192,  kl + hh * 64, D, tid);
        fa_load(st + 16384, vth + (size_t)(hh * 64) * S, S, tid);
        fa_load(st + 24576, vtl + (size_t)(hh * 64) * S, S, tid);
    }
    CP_COMMIT();

    uint32_t qhf[4][4], qlf[4][4];
    float o_acc[8][4] = {};
    float m0 = -1e30f, m1 = -1e30f, l0 = 0.f, l1 = 0.f;

    for (int kb = 0; kb <= qb; kb++) {
        if (kb + 1 <= qb) {
            uint32_t st = sb + 16384 + ((kb + 1) & 1) * 32768;
            fa_load(st,         kh + (size_t)((kb + 1) * 64) * D + hh * 64, D, tid);
            fa_load(st + 8192,  kl + (size_t)((kb + 1) * 64) * D + hh * 64, D, tid);
            fa_load(st + 16384, vth + (size_t)(hh * 64) * S + (kb + 1) * 64, S, tid);
            fa_load(st + 24576, vtl + (size_t)(hh * 64) * S + (kb + 1) * 64, S, tid);
            CP_COMMIT();
            CP_WAIT(1);
        } else {
            CP_WAIT(0);
        }
        __syncthreads();

        if (kb == 0) {
#pragma unroll
            for (int f = 0; f < 4; f++) {
                int row = w * 16 + (lane & 15);
                int jc = (lane >> 4) + f * 2;
                ldsm4(qhf[f], sb + row * 128 + ((jc ^ (row & 7)) << 4));
                ldsm4(qlf[f], sb + 8192 + row * 128 + ((jc ^ (row & 7)) << 4));
            }
        }

        uint32_t st = sb + 16384 + (kb & 1) * 32768;
        float s_acc[8][4] = {};
#pragma unroll
        for (int ks = 0; ks < 4; ks++) {
            uint32_t bh4[4][4], bl4[4][4];
#pragma unroll
            for (int np = 0; np < 4; np++) {
                int row = np * 16 + ((lane >> 4) << 3) + (lane & 7);
                int jc = ((lane >> 3) & 1) + ks * 2;
                ldsm4(bh4[np], st + row * 128 + ((jc ^ (row & 7)) << 4));
                ldsm4(bl4[np], st + 8192 + row * 128 + ((jc ^ (row & 7)) << 4));
            }
#pragma unroll
            for (int nf = 0; nf < 8; nf++) {
                uint32_t* bh = &bh4[nf >> 1][(nf & 1) * 2];
                uint32_t* bl = &bl4[nf >> 1][(nf & 1) * 2];
                mma_bf16(s_acc[nf], qhf[ks], bh);
                mma_bf16(s_acc[nf], qhf[ks], bl);
                mma_bf16(s_acc[nf], qlf[ks], bh);
            }
        }
        int r_lo = qb * 64 + w * 16 + (lane >> 2);
#pragma unroll
        for (int nf = 0; nf < 8; nf++)
#pragma unroll
            for (int e = 0; e < 4; e++) {
                float v = s_acc[nf][e] * 0.125f;
                if (kb == qb) {
                    int key = kb * 64 + nf * 8 + ((lane & 3) << 1) + (e & 1);
                    int qr = r_lo + ((e >> 1) ? 8 : 0);
                    if (key > qr) v = -1e30f;
                }
                s_acc[nf][e] = v;
            }
        float mx0 = -1e30f, mx1 = -1e30f;
#pragma unroll
        for (int nf = 0; nf < 8; nf++) {
            mx0 = fmaxf(mx0, fmaxf(s_acc[nf][0], s_acc[nf][1]));
            mx1 = fmaxf(mx1, fmaxf(s_acc[nf][2], s_acc[nf][3]));
        }
        mx0 = fmaxf(mx0, __shfl_xor_sync(0xffffffffu, mx0, 1));
        mx0 = fmaxf(mx0, __shfl_xor_sync(0xffffffffu, mx0, 2));
        mx1 = fmaxf(mx1, __shfl_xor_sync(0xffffffffu, mx1, 1));
        mx1 = fmaxf(mx1, __shfl_xor_sync(0xffffffffu, mx1, 2));
        float mn0 = fmaxf(m0, mx0), mn1 = fmaxf(m1, mx1);
        float a0 = __expf(m0 - mn0), a1 = __expf(m1 - mn1);
        float sum0 = 0.f, sum1 = 0.f;
#pragma unroll
        for (int nf = 0; nf < 8; nf++) {
            s_acc[nf][0] = __expf(s_acc[nf][0] - mn0);
            s_acc[nf][1] = __expf(s_acc[nf][1] - mn0);
            s_acc[nf][2] = __expf(s_acc[nf][2] - mn1);
            s_acc[nf][3] = __expf(s_acc[nf][3] - mn1);
            sum0 += s_acc[nf][0] + s_acc[nf][1];
            sum1 += s_acc[nf][2] + s_acc[nf][3];
        }
        sum0 += __shfl_xor_sync(0xffffffffu, sum0, 1);
        sum0 += __shfl_xor_sync(0xffffffffu, sum0, 2);
        sum1 += __shfl_xor_sync(0xffffffffu, sum1, 1);
        sum1 += __shfl_xor_sync(0xffffffffu, sum1, 2);
        l0 = l0 * a0 + sum0;
        l1 = l1 * a1 + sum1;
        m0 = mn0; m1 = mn1;
#pragma unroll
        for (int nf = 0; nf < 8; nf++) {
            o_acc[nf][0] *= a0; o_acc[nf][1] *= a0;
            o_acc[nf][2] *= a1; o_acc[nf][3] *= a1;
        }
        uint32_t pph[4][4], ppl[4][4];
#pragma unroll
        for (int g = 0; g < 4; g++) {
            float c0 = s_acc[2 * g][0], c1 = s_acc[2 * g][1];
            float c2 = s_acc[2 * g][2], c3 = s_acc[2 * g][3];
            float d0 = s_acc[2 * g + 1][0], d1 = s_acc[2 * g + 1][1];
            float d2 = s_acc[2 * g + 1][2], d3 = s_acc[2 * g + 1][3];
            pph[g][0] = pack2bf(c0, c1); pph[g][1] = pack2bf(c2, c3);
            pph[g][2] = pack2bf(d0, d1); pph[g][3] = pack2bf(d2, d3);
            ppl[g][0] = pack2bf(c0 - __bfloat162float(__float2bfloat16(c0)),
                                c1 - __bfloat162float(__float2bfloat16(c1)));
            ppl[g][1] = pack2bf(c2 - __bfloat162float(__float2bfloat16(c2)),
                                c3 - __bfloat162float(__float2bfloat16(c3)));
            ppl[g][2] = pack2bf(d0 - __bfloat162float(__float2bfloat16(d0)),
                                d1 - __bfloat162float(__float2bfloat16(d1)));
            ppl[g][3] = pack2bf(d2 - __bfloat162float(__float2bfloat16(d2)),
                                d3 - __bfloat162float(__float2bfloat16(d3)));
        }
        uint32_t sv = st + 16384;
#pragma unroll
        for (int ks = 0; ks < 4; ks++) {
            uint32_t bh4[4][4], bl4[4][4];
#pragma unroll
            for (int np = 0; np < 4; np++) {
                int row = np * 16 + ((lane >> 4) << 3) + (lane & 7);
                int jc = ((lane >> 3) & 1) + ks * 2;
                ldsm4(bh4[np], sv + row * 128 + ((jc ^ (row & 7)) << 4));
                ldsm4(bl4[np], sv + 8192 + row * 128 + ((jc ^ (row & 7)) << 4));
            }
#pragma unroll
            for (int nf = 0; nf < 8; nf++) {
                uint32_t* bh = &bh4[nf >> 1][(nf & 1) * 2];
                uint32_t* bl = &bl4[nf >> 1][(nf & 1) * 2];
                mma_bf16(o_acc[nf], pph[ks], bh);
                mma_bf16(o_acc[nf], ppl[ks], bh);
                mma_bf16(o_acc[nf], pph[ks], bl);
            }
        }
        __syncthreads();
    }

    float inv0 = 1.f / l0, inv1 = 1.f / l1;
    int row0 = qb * 64 + w * 16 + (lane >> 2);
#pragma unroll
    for (int nf = 0; nf < 8; nf++) {
        int col = hh * 64 + nf * 8 + ((lane & 3) << 1);
        float v0 = o_acc[nf][0] * inv0, v1 = o_acc[nf][1] * inv0;
        float v2 = o_acc[nf][2] * inv1, v3 = o_acc[nf][3] * inv1;
        float h0 = __bfloat162float(__float2bfloat16(v0));
        float h1 = __bfloat162float(__float2bfloat16(v1));
        float h2 = __bfloat162float(__float2bfloat16(v2));
        float h3 = __bfloat162float(__float2bfloat16(v3));
        *(uint32_t*)(oh + (size_t)row0 * D + col) = pack2bf(v0, v1);
        *(uint32_t*)(oh + (size_t)(row0 + 8) * D + col) = pack2bf(v2, v3);
        *(uint32_t*)(ol + (size_t)row0 * D + col) = pack2bf(v0 - h0, v1 - h1);
        *(uint32_t*)(ol + (size_t)(row0 + 8) * D + col) = pack2bf(v2 - h2, v3 - h3);
    }
}

// ---------------------------------------------------------------------------
// flat weight split: 8 elems/thread (R9 config: best measured), grid = n/2048
// ---------------------------------------------------------------------------
__global__ __launch_bounds__(256) void k_split_flat(const float* __restrict__ W,
                                                    __nv_bfloat16* __restrict__ th,
                                                    __nv_bfloat16* __restrict__ tl) {
    size_t gid = (size_t)blockIdx.x * 256 + threadIdx.x;
    float4 a = ((const float4*)W)[2 * gid];
    float4 b = ((const float4*)W)[2 * gid + 1];
    uint4 uh, ul;
    uh.x = pack2bf(a.x, a.y); uh.y = pack2bf(a.z, a.w);
    uh.z = pack2bf(b.x, b.y); uh.w = pack2bf(b.z, b.w);
    ul.x = pack2bf(a.x - __bfloat162float(__float2bfloat16(a.x)),
                   a.y - __bfloat162float(__float2bfloat16(a.y)));
    ul.y = pack2bf(a.z - __bfloat162float(__float2bfloat16(a.z)),
                   a.w - __bfloat162float(__float2bfloat16(a.w)));
    ul.z = pack2bf(b.x - __bfloat162float(__float2bfloat16(b.x)),
                   b.y - __bfloat162float(__float2bfloat16(b.y)));
    ul.w = pack2bf(b.z - __bfloat162float(__float2bfloat16(b.z)),
                   b.w - __bfloat162float(__float2bfloat16(b.w)));
    ((uint4*)th)[gid] = uh;
    ((uint4*)tl)[gid] = ul;
}

// ---------------------------------------------------------------------------
// embedding + positional encoding
// ---------------------------------------------------------------------------
__global__ __launch_bounds__(256) void k_embed(const int* __restrict__ x,
                                               const float* __restrict__ emb,
                                               float* __restrict__ h) {
    int s = blockIdx.y;
    int d = blockIdx.x * 256 + threadIdx.x;
    int tok = x[s];
    float e = emb[(size_t)tok * D + d];
    int i2 = d & ~1;
    float freq = expf((float)i2 * (-9.210340371976184f / (float)D));
    float ang = (float)s * freq;
    float pe = (d & 1) ? cosf(ang) : sinf(ang);
    h[(size_t)s * D + d] = e + pe;
}

// ---------------------------------------------------------------------------
// layernorm -> bf16 hi/lo (warp-shuffle reduce, 1 barrier)
// ---------------------------------------------------------------------------
__global__ __launch_bounds__(256) void k_ln(const float* __restrict__ in,
                                            __nv_bfloat16* __restrict__ oh,
                                            __nv_bfloat16* __restrict__ ol,
                                            const float* __restrict__ w,
                                            const float* __restrict__ b) {
    int row = blockIdx.x;
    const float* xr = in + (size_t)row * D;
    int t = threadIdx.x, wid = t >> 5, lane = t & 31;
    __shared__ float w1s[8], w2s[8];
    float s1 = 0.f, s2 = 0.f;
    for (int d = t; d < D; d += 256) {
        float v = xr[d];
        s1 += v; s2 += v * v;
    }
#pragma unroll
    for (int o = 16; o > 0; o >>= 1) {
        s1 += __shfl_xor_sync(0xffffffffu, s1, o);
        s2 += __shfl_xor_sync(0xffffffffu, s2, o);
    }
    if (lane == 0) { w1s[wid] = s1; w2s[wid] = s2; }
    __syncthreads();
    float t1 = 0.f, t2 = 0.f;
#pragma unroll
    for (int i = 0; i < 8; i++) { t1 += w1s[i]; t2 += w2s[i]; }
    float mean = t1 * (1.0f / D);
    float var = t2 * (1.0f / D) - mean * mean;
    float rstd = rsqrtf(var + EPSF);
    for (int d = t; d < D; d += 256) {
        float v = (xr[d] - mean) * rstd * w[d] + b[d];
        __nv_bfloat16 hv = __float2bfloat16(v);
        oh[(size_t)row * D + d] = hv;
        ol[(size_t)row * D + d] = __float2bfloat16(v - __bfloat162float(hv));
    }
}

// ---------------------------------------------------------------------------
// launch orchestration (two streams: s1 compute, s2 weight prep)
// ---------------------------------------------------------------------------
extern "C" void kernel_launch(void* const* d_in, const int* in_sizes, int n_in,
                              void* d_out, int out_size) {
    (void)in_sizes; (void)n_in; (void)out_size;
    const int*   x      = (const int*)d_in[0];
    const float* emb    = (const float*)d_in[1];
    const float* Wq     = (const float*)d_in[2];
    const float* Wk     = (const float*)d_in[3];
    const float* Wv     = (const float*)d_in[4];
    const float* Wo     = (const float*)d_in[5];
    const float* bo     = (const float*)d_in[6];
    const float* ln1_w  = (const float*)d_in[7];
    const float* ln1_b  = (const float*)d_in[8];
    const float* W1     = (const float*)d_in[9];
    const float* b1     = (const float*)d_in[10];
    const float* W2     = (const float*)d_in[11];
    const float* b2     = (const float*)d_in[12];
    const float* ln2_w  = (const float*)d_in[13];
    const float* ln2_b  = (const float*)d_in[14];
    const float* fn_w   = (const float*)d_in[15];
    const float* fn_b   = (const float*)d_in[16];
    const float* lmhead = (const float*)d_in[17];
    float* out = (float*)d_out;

    static float* ph = nullptr;
    static __nv_bfloat16 *acth, *actl, *ffh, *ffl, *qh, *ql, *kh, *kl, *vth, *vtl,
                         *qkvh, *qkvl, *woh, *wol, *w1h, *w1l, *w2h, *w2l, *lmh, *lml;
    static cudaStream_t s1, s2;
    static cudaEvent_t evFork, evW[L], evLM, evDone;
    if (!ph) {
        cudaGetSymbolAddress((void**)&ph,   g_h);
        cudaGetSymbolAddress((void**)&acth, g_act_h);
        cudaGetSymbolAddress((void**)&actl, g_act_l);
        cudaGetSymbolAddress((void**)&ffh,  g_ff_h);
        cudaGetSymbolAddress((void**)&ffl,  g_ff_l);
        cudaGetSymbolAddress((void**)&qh,   g_qh);
        cudaGetSymbolAddress((void**)&ql,   g_ql);
        cudaGetSymbolAddress((void**)&kh,   g_kh);
        cudaGetSymbolAddress((void**)&kl,   g_kl);
        cudaGetSymbolAddress((void**)&vth,  g_vth);
        cudaGetSymbolAddress((void**)&vtl,  g_vtl);
        cudaGetSymbolAddress((void**)&qkvh, g_qkv_h);
        cudaGetSymbolAddress((void**)&qkvl, g_qkv_l);
        cudaGetSymbolAddress((void**)&woh,  g_wo_h);
        cudaGetSymbolAddress((void**)&wol,  g_wo_l);
        cudaGetSymbolAddress((void**)&w1h,  g_w1_h);
        cudaGetSymbolAddress((void**)&w1l,  g_w1_l);
        cudaGetSymbolAddress((void**)&w2h,  g_w2_h);
        cudaGetSymbolAddress((void**)&w2l,  g_w2_l);
        cudaGetSymbolAddress((void**)&lmh,  g_lm_h);
        cudaGetSymbolAddress((void**)&lml,  g_lm_l);
        cudaFuncSetAttribute(k_gemm_f32,     cudaFuncAttributeMaxDynamicSharedMemorySize, MG_SMEM);
        cudaFuncSetAttribute(k_gemm_f32_t64, cudaFuncAttributeMaxDynamicSharedMemorySize, T64_SMEM);
        cudaFuncSetAttribute(k_gemm_bf16,    cudaFuncAttributeMaxDynamicSharedMemorySize, MG_SMEM);
        cudaFuncSetAttribute(k_qkv_gemm,     cudaFuncAttributeMaxDynamicSharedMemorySize, MG_SMEM);
        cudaFuncSetAttribute(k_flash,        cudaFuncAttributeMaxDynamicSharedMemorySize, FA_SMEM);
        cudaStreamCreateWithFlags(&s1, cudaStreamNonBlocking);
        cudaStreamCreateWithFlags(&s2, cudaStreamNonBlocking);
        cudaEventCreateWithFlags(&evFork, cudaEventDisableTiming);
        for (int l = 0; l < L; l++) cudaEventCreateWithFlags(&evW[l], cudaEventDisableTiming);
        cudaEventCreateWithFlags(&evLM, cudaEventDisableTiming);
        cudaEventCreateWithFlags(&evDone, cudaEventDisableTiming);
    }

    // fork
    cudaEventRecord(evFork, 0);
    cudaStreamWaitEvent(s1, evFork, 0);
    cudaStreamWaitEvent(s2, evFork, 0);

    // s2: weight prep (8 elts/thread; grid = n/2048)
    const int gDD = D * D / 2048;
    const int gDF = D * FF / 2048;
    for (int l = 0; l < L; l++) {
        size_t wo = (size_t)l * D * D;
        size_t qo = (size_t)l * 3 * D * D;
        k_split_flat<<<gDD, 256, 0, s2>>>(Wq + wo, qkvh + qo,             qkvl + qo);
        k_split_flat<<<gDD, 256, 0, s2>>>(Wk + wo, qkvh + qo + D * D,     qkvl + qo + D * D);
        k_split_flat<<<gDD, 256, 0, s2>>>(Wv + wo, qkvh + qo + 2 * D * D, qkvl + qo + 2 * D * D);
        k_split_flat<<<gDD, 256, 0, s2>>>(Wo + wo, woh + wo, wol + wo);
        k_split_flat<<<gDF, 256, 0, s2>>>(W1 + (size_t)l * D * FF,
                                          w1h + (size_t)l * D * FF, w1l + (size_t)l * D * FF);
        k_split_flat<<<gDF, 256, 0, s2>>>(W2 + (size_t)l * FF * D,
                                          w2h + (size_t)l * FF * D, w2l + (size_t)l * FF * D);
        cudaEventRecord(evW[l], s2);
    }
    k_split_flat<<<(int)((size_t)D * V / 2048), 256, 0, s2>>>(lmhead, lmh, lml);
    cudaEventRecord(evLM, s2);

    // s1: compute
    k_embed<<<dim3(D / 256, S), 256, 0, s1>>>(x, emb, ph);

    for (int l = 0; l < L; l++) {
        size_t wo = (size_t)l * D * D;
        size_t qo = (size_t)l * 3 * D * D;
        cudaStreamWaitEvent(s1, evW[l], 0);
        // --- attention ---
        k_ln<<<S, 256, 0, s1>>>(ph, acth, actl, ln1_w + (size_t)l * D, ln1_b + (size_t)l * D);
        k_qkv_gemm<<<dim3(3 * D / 128, S / 128), 256, MG_SMEM, s1>>>(
            acth, actl, qkvh + qo, qkvl + qo, qh, ql, kh, kl, vth, vtl);
        k_flash<<<dim3(S / 64, H), 128, FA_SMEM, s1>>>(qh, ql, kh, kl, vth, vtl, acth, actl);
        k_gemm_f32_t64<<<dim3(D / 64, S / 64), 256, T64_SMEM, s1>>>(
            acth, actl, woh + wo, wol + wo, bo + (size_t)l * D, ph, ph, D, D, D);
        // --- FFN ---
        k_ln<<<S, 256, 0, s1>>>(ph, acth, actl, ln2_w + (size_t)l * D, ln2_b + (size_t)l * D);
        k_gemm_bf16<<<dim3(FF / 128, S / 128), 256, MG_SMEM, s1>>>(
            acth, actl, w1h + (size_t)l * D * FF, w1l + (size_t)l * D * FF,
            b1 + (size_t)l * FF, ffh, ffl, D, FF, FF, 1);
        k_gemm_f32_t64<<<dim3(D / 64, S / 64), 256, T64_SMEM, s1>>>(
            ffh, ffl, w2h + (size_t)l * FF * D, w2l + (size_t)l * FF * D,
            b2 + (size_t)l * D, ph, ph, FF, D, D);
    }

    // final LN + LM head
    cudaStreamWaitEvent(s1, evLM, 0);
    k_ln<<<S, 256, 0, s1>>>(ph, acth, actl, fn_w, fn_b);
    k_gemm_f32<<<dim3(V / 128, S / 128), 256, MG_SMEM, s1>>>(
        acth, actl, lmh, lml, nullptr, nullptr, out, D, V, V);

    // join
    cudaEventRecord(evDone, s1);
    cudaStreamWaitEvent(0, evDone, 0);
}

// round 13
// speedup vs baseline: 1.0138x; 1.0009x over previous
#include <cuda_runtime.h>
#include <cuda_bf16.h>
#include <math.h>
#include <stdint.h>

#define S 1024
#define D 1024
#define H 16
#define HD 64
#define L 4
#define FF 4096
#define V 32000
#define EPSF 1e-5f

// ---------------------------------------------------------------------------
// device scratch
// ---------------------------------------------------------------------------
__device__ __align__(16) float g_h[S * D];

__device__ __align__(16) __nv_bfloat16 g_act_h[S * FF];
__device__ __align__(16) __nv_bfloat16 g_act_l[S * FF];
__device__ __align__(16) __nv_bfloat16 g_ff_h[S * FF];
__device__ __align__(16) __nv_bfloat16 g_ff_l[S * FF];
__device__ __align__(16) __nv_bfloat16 g_qh[S * D];
__device__ __align__(16) __nv_bfloat16 g_ql[S * D];
__device__ __align__(16) __nv_bfloat16 g_kh[S * D];
__device__ __align__(16) __nv_bfloat16 g_kl[S * D];
__device__ __align__(16) __nv_bfloat16 g_vth[D * S];
__device__ __align__(16) __nv_bfloat16 g_vtl[D * S];

// weights: K-major [K,N] bf16 hi/lo
__device__ __align__(16) __nv_bfloat16 g_qkv_h[(size_t)L * 3 * D * D];
__device__ __align__(16) __nv_bfloat16 g_qkv_l[(size_t)L * 3 * D * D];
__device__ __align__(16) __nv_bfloat16 g_wo_h[(size_t)L * D * D];
__device__ __align__(16) __nv_bfloat16 g_wo_l[(size_t)L * D * D];
__device__ __align__(16) __nv_bfloat16 g_w1_h[(size_t)L * D * FF];
__device__ __align__(16) __nv_bfloat16 g_w1_l[(size_t)L * D * FF];
__device__ __align__(16) __nv_bfloat16 g_w2_h[(size_t)L * FF * D];
__device__ __align__(16) __nv_bfloat16 g_w2_l[(size_t)L * FF * D];
__device__ __align__(16) __nv_bfloat16 g_lm_h[(size_t)D * V];
__device__ __align__(16) __nv_bfloat16 g_lm_l[(size_t)D * V];

// ---------------------------------------------------------------------------
// PTX helpers
// ---------------------------------------------------------------------------
__device__ __forceinline__ uint32_t smem_u32(const void* p) {
    uint32_t a;
    asm("{ .reg .u64 t; cvta.to.shared.u64 t, %1; cvt.u32.u64 %0, t; }" : "=r"(a) : "l"(p));
    return a;
}
#define CP16(dst, src) \
    asm volatile("cp.async.cg.shared.global [%0], [%1], 16;" :: "r"(dst), "l"(src))
#define CP_COMMIT() asm volatile("cp.async.commit_group;" ::: "memory")
#define CP_WAIT(n)  asm volatile("cp.async.wait_group %0;" :: "n"(n) : "memory")

__device__ __forceinline__ void ldsm4(uint32_t* r, uint32_t addr) {
    asm volatile("ldmatrix.sync.aligned.m8n8.x4.shared.b16 {%0,%1,%2,%3}, [%4];"
                 : "=r"(r[0]), "=r"(r[1]), "=r"(r[2]), "=r"(r[3]) : "r"(addr));
}
__device__ __forceinline__ void ldsm4t(uint32_t* r, uint32_t addr) {
    asm volatile("ldmatrix.sync.aligned.m8n8.x4.trans.shared.b16 {%0,%1,%2,%3}, [%4];"
                 : "=r"(r[0]), "=r"(r[1]), "=r"(r[2]), "=r"(r[3]) : "r"(addr));
}
__device__ __forceinline__ void mma_bf16(float* d, const uint32_t* a, const uint32_t* b) {
    asm volatile(
        "mma.sync.aligned.m16n8k16.row.col.f32.bf16.bf16.f32 "
        "{%0,%1,%2,%3}, {%4,%5,%6,%7}, {%8,%9}, {%0,%1,%2,%3};"
        : "+f"(d[0]), "+f"(d[1]), "+f"(d[2]), "+f"(d[3])
        : "r"(a[0]), "r"(a[1]), "r"(a[2]), "r"(a[3]), "r"(b[0]), "r"(b[1]));
}
__device__ __forceinline__ uint32_t pack2bf(float a, float b) {
    unsigned short ra = __bfloat16_as_ushort(__float2bfloat16(a));
    unsigned short rb = __bfloat16_as_ushort(__float2bfloat16(b));
    return (uint32_t)ra | ((uint32_t)rb << 16);
}

// ---------------------------------------------------------------------------
// GEMM cores. A row-major hi/lo [M,K]; B K-major hi/lo [K,N]. 3-stage pipe.
// ---------------------------------------------------------------------------
#define MG_SMEM (3 * 32768)
#define T64_SMEM (3 * 16384)

__device__ __forceinline__ void tile_load_A(uint32_t sdst,
                                            const __nv_bfloat16* gh,
                                            const __nv_bfloat16* gl,
                                            int ld, int k0, int tid) {
#pragma unroll
    for (int i = 0; i < 4; i++) {
        int cid = i * 256 + tid;
        int row = cid >> 3, sub = cid & 7;
        const __nv_bfloat16* src =
            ((sub & 4) ? gl : gh) + (size_t)row * ld + k0 + (sub & 3) * 8;
        uint32_t dst = sdst + row * 128 + ((sub ^ (row & 7)) << 4);
        CP16(dst, src);
    }
}

__device__ __forceinline__ void tile_load_A64(uint32_t sdst,
                                              const __nv_bfloat16* gh,
                                              const __nv_bfloat16* gl,
                                              int ld, int k0, int tid) {
#pragma unroll
    for (int i = 0; i < 2; i++) {
        int cid = i * 256 + tid;
        int row = cid >> 3, sub = cid & 7;
        const __nv_bfloat16* src =
            ((sub & 4) ? gl : gh) + (size_t)row * ld + k0 + (sub & 3) * 8;
        uint32_t dst = sdst + row * 128 + ((sub ^ (row & 7)) << 4);
        CP16(dst, src);
    }
}

__device__ __forceinline__ void tile_load_B(uint32_t sdst,
                                            const __nv_bfloat16* gh,
                                            const __nv_bfloat16* gl,
                                            int ldb, int bn, int k0, int tid) {
#pragma unroll
    for (int i = 0; i < 4; i++) {
        int cid = i * 256 + tid;
        int half = cid >> 9;
        int rem = cid & 511;
        int row = rem >> 4, c = rem & 15;
        const __nv_bfloat16* src =
            (half ? gl : gh) + (size_t)(k0 + row) * ldb + bn + c * 8;
        uint32_t dst = sdst + half * 8192 + row * 256 +
                       ((c ^ ((row & 7) << 1)) << 4);
        CP16(dst, src);
    }
}

__device__ __forceinline__ void tile_load_B64(uint32_t sdst,
                                              const __nv_bfloat16* gh,
                                              const __nv_bfloat16* gl,
                                              int ldb, int bn, int k0, int tid) {
#pragma unroll
    for (int i = 0; i < 2; i++) {
        int cid = i * 256 + tid;
        int half = cid >> 8;
        int rem = cid & 255;
        int row = rem >> 3, c = rem & 7;
        const __nv_bfloat16* src =
            (half ? gl : gh) + (size_t)(k0 + row) * ldb + bn + c * 8;
        uint32_t dst = sdst + half * 4096 + row * 128 + ((c ^ (row & 7)) << 4);
        CP16(dst, src);
    }
}

__device__ __forceinline__ void gemm_core(float (&acc)[4][4][4],
                                          const __nv_bfloat16* Ah, const __nv_bfloat16* Al,
                                          const __nv_bfloat16* Bh, const __nv_bfloat16* Bl,
                                          int K, int ldb, int bm, int bn, char* smem) {
    const int tid = threadIdx.x;
    const int wid = tid >> 5, lane = tid & 31;
    const int wm = (wid >> 2) * 64, wn = (wid & 3) * 32;
    uint32_t sbase = smem_u32(smem);

    const __nv_bfloat16* ah_g = Ah + (size_t)bm * K;
    const __nv_bfloat16* al_g = Al + (size_t)bm * K;

    const int nt = K >> 5;
    tile_load_A(sbase, ah_g, al_g, K, 0, tid);
    tile_load_B(sbase + 16384, Bh, Bl, ldb, bn, 0, tid);
    CP_COMMIT();
    tile_load_A(sbase + 32768, ah_g, al_g, K, 32, tid);
    tile_load_B(sbase + 32768 + 16384, Bh, Bl, ldb, bn, 32, tid);
    CP_COMMIT();

    const int kr_base = (lane & 7) + ((lane >> 3) & 1) * 8;
    const int nc8 = (lane >> 4);

    int br = 0, bw = 2;
    for (int t = 0; t < nt; t++) {
        if (t + 1 < nt) { CP_WAIT(1); } else { CP_WAIT(0); }
        __syncthreads();
        if (t + 2 < nt) {
            uint32_t nb = sbase + bw * 32768;
            tile_load_A(nb, ah_g, al_g, K, (t + 2) << 5, tid);
            tile_load_B(nb + 16384, Bh, Bl, ldb, bn, (t + 2) << 5, tid);
            CP_COMMIT();
        }

        uint32_t sA = sbase + br * 32768;
        uint32_t sB = sA + 16384;
#pragma unroll
        for (int ks = 0; ks < 2; ks++) {
            uint32_t bhf[2][4], blf[2][4];
#pragma unroll
            for (int np = 0; np < 2; np++) {
                int krow = ks * 16 + kr_base;
                int ncol = wn + np * 16 + nc8 * 8;
                int c = ncol >> 3;
                uint32_t a = sB + krow * 256 + ((c ^ ((krow & 7) << 1)) << 4);
                ldsm4t(bhf[np], a);
                ldsm4t(blf[np], a + 8192);
            }
#pragma unroll
            for (int mp = 0; mp < 2; mp++) {
                uint32_t ahf[2][4], alf[2][4];
#pragma unroll
                for (int f2 = 0; f2 < 2; f2++) {
                    int row = wm + (mp * 2 + f2) * 16 + (lane & 15);
                    int jc = (lane >> 4) + ks * 2;
                    ldsm4(ahf[f2], sA + row * 128 + ((jc ^ (row & 7)) << 4));
                    ldsm4(alf[f2], sA + row * 128 + (((jc + 4) ^ (row & 7)) << 4));
                }
#pragma unroll
                for (int m2 = 0; m2 < 2; m2++)
#pragma unroll
                    for (int nf = 0; nf < 4; nf++) {
                        uint32_t* bhp = &bhf[nf >> 1][(nf & 1) * 2];
                        uint32_t* blp = &blf[nf >> 1][(nf & 1) * 2];
                        float* ac = acc[mp * 2 + m2][nf];
                        mma_bf16(ac, ahf[m2], bhp);
                        mma_bf16(ac, ahf[m2], blp);
                        mma_bf16(ac, alf[m2], bhp);
                    }
            }
        }
        br = (br == 2) ? 0 : br + 1;
        bw = (bw == 2) ? 0 : bw + 1;
    }
}

__device__ __forceinline__ void gemm_core_t64(float (&acc)[4][4],
                                              const __nv_bfloat16* Ah, const __nv_bfloat16* Al,
                                              const __nv_bfloat16* Bh, const __nv_bfloat16* Bl,
                                              int K, int ldb, int bm, int bn, char* smem) {
    const int tid = threadIdx.x;
    const int wid = tid >> 5, lane = tid & 31;
    const int wm = (wid >> 1) * 16, wn = (wid & 1) * 32;
    uint32_t sbase = smem_u32(smem);

    const __nv_bfloat16* ah_g = Ah + (size_t)bm * K;
    const __nv_bfloat16* al_g = Al + (size_t)bm * K;

    const int nt = K >> 5;
    tile_load_A64(sbase, ah_g, al_g, K, 0, tid);
    tile_load_B64(sbase + 8192, Bh, Bl, ldb, bn, 0, tid);
    CP_COMMIT();
    tile_load_A64(sbase + 16384, ah_g, al_g, K, 32, tid);
    tile_load_B64(sbase + 16384 + 8192, Bh, Bl, ldb, bn, 32, tid);
    CP_COMMIT();

    const int kr_base = (lane & 7) + ((lane >> 3) & 1) * 8;
    const int nc8 = (lane >> 4);

    int br = 0, bw = 2;
    for (int t = 0; t < nt; t++) {
        if (t + 1 < nt) { CP_WAIT(1); } else { CP_WAIT(0); }
        __syncthreads();
        if (t + 2 < nt) {
            uint32_t nb = sbase + bw * 16384;
            tile_load_A64(nb, ah_g, al_g, K, (t + 2) << 5, tid);
            tile_load_B64(nb + 8192, Bh, Bl, ldb, bn, (t + 2) << 5, tid);
            CP_COMMIT();
        }

        uint32_t sA = sbase + br * 16384;
        uint32_t sB = sA + 8192;
#pragma unroll
        for (int ks = 0; ks < 2; ks++) {
            uint32_t bhf[2][4], blf[2][4];
#pragma unroll
            for (int np = 0; np < 2; np++) {
                int krow = ks * 16 + kr_base;
                int ncol = wn + np * 16 + nc8 * 8;
                int c = ncol >> 3;
                uint32_t a = sB + krow * 128 + ((c ^ (krow & 7)) << 4);
                ldsm4t(bhf[np], a);
                ldsm4t(blf[np], a + 4096);
            }
            uint32_t ahf[4], alf[4];
            {
                int row = wm + (lane & 15);
                int jc = (lane >> 4) + ks * 2;
                ldsm4(ahf, sA + row * 128 + ((jc ^ (row & 7)) << 4));
                ldsm4(alf, sA + row * 128 + (((jc + 4) ^ (row & 7)) << 4));
            }
#pragma unroll
            for (int nf = 0; nf < 4; nf++) {
                uint32_t* bhp = &bhf[nf >> 1][(nf & 1) * 2];
                uint32_t* blp = &blf[nf >> 1][(nf & 1) * 2];
                float* ac = acc[nf];
                mma_bf16(ac, ahf, bhp);
                mma_bf16(ac, ahf, blp);
                mma_bf16(ac, alf, bhp);
            }
        }
        br = (br == 2) ? 0 : br + 1;
        bw = (bw == 2) ? 0 : bw + 1;
    }
}

// fp32 output (+bias, +res), 128-wide N
__global__ __launch_bounds__(256, 2)
void k_gemm_f32(const __nv_bfloat16* __restrict__ Ah, const __nv_bfloat16* __restrict__ Al,
                const __nv_bfloat16* __restrict__ Bh, const __nv_bfloat16* __restrict__ Bl,
                const float* __restrict__ bias, const float* __restrict__ res,
                float* __restrict__ C, int K, int ldb, int ldc) {
    extern __shared__ char smem[];
    const int tid = threadIdx.x, wid = tid >> 5, lane = tid & 31;
    const int bm = blockIdx.y * 128, bn = blockIdx.x * 128;
    const int wm = (wid >> 2) * 64, wn = (wid & 3) * 32;
    float acc[4][4][4] = {};
    gemm_core(acc, Ah, Al, Bh, Bl, K, ldb, bm, bn, smem);
#pragma unroll
    for (int m = 0; m < 4; m++) {
        int r0 = bm + wm + m * 16 + (lane >> 2);
#pragma unroll
        for (int nf = 0; nf < 4; nf++) {
            int col = bn + wn + nf * 8 + ((lane & 3) << 1);
            float v0 = acc[m][nf][0], v1 = acc[m][nf][1];
            float v2 = acc[m][nf][2], v3 = acc[m][nf][3];
            if (bias) {
                float b0 = bias[col], b1 = bias[col + 1];
                v0 += b0; v1 += b1; v2 += b0; v3 += b1;
            }
            if (res) {
                const float* rr0 = res + (size_t)r0 * ldc + col;
                const float* rr1 = res + (size_t)(r0 + 8) * ldc + col;
                v0 += rr0[0]; v1 += rr0[1]; v2 += rr1[0]; v3 += rr1[1];
            }
            *(float2*)(C + (size_t)r0 * ldc + col) = make_float2(v0, v1);
            *(float2*)(C + (size_t)(r0 + 8) * ldc + col) = make_float2(v2, v3);
        }
    }
}

// fp32 output (+bias, +res), 64x64 tile — Wo / FFN2
__global__ __launch_bounds__(256, 2)
void k_gemm_f32_t64(const __nv_bfloat16* __restrict__ Ah, const __nv_bfloat16* __restrict__ Al,
                    const __nv_bfloat16* __restrict__ Bh, const __nv_bfloat16* __restrict__ Bl,
                    const float* __restrict__ bias, const float* __restrict__ res,
                    float* __restrict__ C, int K, int ldb, int ldc) {
    extern __shared__ char smem[];
    const int tid = threadIdx.x, wid = tid >> 5, lane = tid & 31;
    const int bm = blockIdx.y * 64, bn = blockIdx.x * 64;
    const int wm = (wid >> 1) * 16, wn = (wid & 1) * 32;
    float acc[4][4] = {};
    gemm_core_t64(acc, Ah, Al, Bh, Bl, K, ldb, bm, bn, smem);
    int r0 = bm + wm + (lane >> 2);
#pragma unroll
    for (int nf = 0; nf < 4; nf++) {
        int col = bn + wn + nf * 8 + ((lane & 3) << 1);
        float v0 = acc[nf][0], v1 = acc[nf][1];
        float v2 = acc[nf][2], v3 = acc[nf][3];
        if (bias) {
            float b0 = bias[col], b1 = bias[col + 1];
            v0 += b0; v1 += b1; v2 += b0; v3 += b1;
        }
        if (res) {
            const float* rr0 = res + (size_t)r0 * ldc + col;
            const float* rr1 = res + (size_t)(r0 + 8) * ldc + col;
            v0 += rr0[0]; v1 += rr0[1]; v2 += rr1[0]; v3 += rr1[1];
        }
        *(float2*)(C + (size_t)r0 * ldc + col) = make_float2(v0, v1);
        *(float2*)(C + (size_t)(r0 + 8) * ldc + col) = make_float2(v2, v3);
    }
}

// bf16 hi/lo output (+bias, relu) — FFN1
__global__ __launch_bounds__(256, 2)
void k_gemm_bf16(const __nv_bfloat16* __restrict__ Ah, const __nv_bfloat16* __restrict__ Al,
                 const __nv_bfloat16* __restrict__ Bh, const __nv_bfloat16* __restrict__ Bl,
                 const float* __restrict__ bias,
                 __nv_bfloat16* __restrict__ Ch, __nv_bfloat16* __restrict__ Cl,
                 int K, int ldb, int ldc, int relu) {
    extern __shared__ char smem[];
    const int tid = threadIdx.x, wid = tid >> 5, lane = tid & 31;
    const int bm = blockIdx.y * 128, bn = blockIdx.x * 128;
    const int wm = (wid >> 2) * 64, wn = (wid & 3) * 32;
    float acc[4][4][4] = {};
    gemm_core(acc, Ah, Al, Bh, Bl, K, ldb, bm, bn, smem);
#pragma unroll
    for (int m = 0; m < 4; m++) {
        int r0 = bm + wm + m * 16 + (lane >> 2);
#pragma unroll
        for (int nf = 0; nf < 4; nf++) {
            int col = bn + wn + nf * 8 + ((lane & 3) << 1);
            float v[4] = {acc[m][nf][0], acc[m][nf][1], acc[m][nf][2], acc[m][nf][3]};
            if (bias) {
                float b0 = bias[col], b1 = bias[col + 1];
                v[0] += b0; v[1] += b1; v[2] += b0; v[3] += b1;
            }
            if (relu) {
#pragma unroll
                for (int e = 0; e < 4; e++) v[e] = fmaxf(v[e], 0.f);
            }
            float h0 = __bfloat162float(__float2bfloat16(v[0]));
            float h1 = __bfloat162float(__float2bfloat16(v[1]));
            float h2 = __bfloat162float(__float2bfloat16(v[2]));
            float h3 = __bfloat162float(__float2bfloat16(v[3]));
            *(uint32_t*)(Ch + (size_t)r0 * ldc + col) = pack2bf(v[0], v[1]);
            *(uint32_t*)(Ch + (size_t)(r0 + 8) * ldc + col) = pack2bf(v[2], v[3]);
            *(uint32_t*)(Cl + (size_t)r0 * ldc + col) = pack2bf(v[0] - h0, v[1] - h1);
            *(uint32_t*)(Cl + (size_t)(r0 + 8) * ldc + col) = pack2bf(v[2] - h2, v[3] - h3);
        }
    }
}

// QKV gemm: B = [3][D,D]; cols [0,D)->q, [D,2D)->k, [2D,3D)->vT via smem
__global__ __launch_bounds__(256, 2)
void k_qkv_gemm(const __nv_bfloat16* __restrict__ Ah, const __nv_bfloat16* __restrict__ Al,
                const __nv_bfloat16* __restrict__ Bh, const __nv_bfloat16* __restrict__ Bl,
                __nv_bfloat16* __restrict__ qh, __nv_bfloat16* __restrict__ ql,
                __nv_bfloat16* __restrict__ kh, __nv_bfloat16* __restrict__ kl,
                __nv_bfloat16* __restrict__ vth, __nv_bfloat16* __restrict__ vtl) {
    extern __shared__ char smem[];
    const int tid = threadIdx.x, wid = tid >> 5, lane = tid & 31;
    const int bm = blockIdx.y * 128, bn = blockIdx.x * 128;
    const int wm = (wid >> 2) * 64, wn = (wid & 3) * 32;
    const int widx = bn >> 10;
    const int bn_eff = bn & 1023;
    float acc[4][4][4] = {};
    gemm_core(acc, Ah, Al, Bh + (size_t)widx * D * D, Bl + (size_t)widx * D * D,
              D, D, bm, bn_eff, smem);

    if (widx < 2) {
        __nv_bfloat16* oh = (widx == 0) ? qh : kh;
        __nv_bfloat16* ol = (widx == 0) ? ql : kl;
#pragma unroll
        for (int m = 0; m < 4; m++) {
            int r0 = bm + wm + m * 16 + (lane >> 2);
#pragma unroll
            for (int nf = 0; nf < 4; nf++) {
                int col = bn_eff + wn + nf * 8 + ((lane & 3) << 1);
                float v0 = acc[m][nf][0], v1 = acc[m][nf][1];
                float v2 = acc[m][nf][2], v3 = acc[m][nf][3];
                float h0 = __bfloat162float(__float2bfloat16(v0));
                float h1 = __bfloat162float(__float2bfloat16(v1));
                float h2 = __bfloat162float(__float2bfloat16(v2));
                float h3 = __bfloat162float(__float2bfloat16(v3));
                *(uint32_t*)(oh + (size_t)r0 * D + col) = pack2bf(v0, v1);
                *(uint32_t*)(oh + (size_t)(r0 + 8) * D + col) = pack2bf(v2, v3);
                *(uint32_t*)(ol + (size_t)r0 * D + col) = pack2bf(v0 - h0, v1 - h1);
                *(uint32_t*)(ol + (size_t)(r0 + 8) * D + col) = pack2bf(v2 - h2, v3 - h3);
            }
        }
    } else {
        __syncthreads();
        __nv_bfloat16* sv = (__nv_bfloat16*)smem;
#pragma unroll
        for (int part = 0; part < 2; part++) {
#pragma unroll
            for (int m = 0; m < 4; m++) {
#pragma unroll
                for (int nf = 0; nf < 4; nf++) {
#pragma unroll
                    for (int e = 0; e < 4; e++) {
                        int rl = wm + m * 16 + (lane >> 2) + ((e >> 1) ? 8 : 0);
                        int cl = wn + nf * 8 + ((lane & 3) << 1) + (e & 1);
                        float v = acc[m][nf][e];
                        float hv = __bfloat162float(__float2bfloat16(v));
                        sv[cl * 136 + rl] = __float2bfloat16(part ? (v - hv) : v);
                    }
                }
            }
            __syncthreads();
            int col = tid >> 1, half = tid & 1;
            const uint4* src = (const uint4*)(smem + col * 272 + half * 128);
            __nv_bfloat16* dst = (part ? vtl : vth) +
                                 (size_t)(bn_eff + col) * S + bm + half * 64;
#pragma unroll
            for (int j = 0; j < 8; j++) ((uint4*)dst)[j] = src[j];
            __syncthreads();
        }
    }
}

// ---------------------------------------------------------------------------
// flash attention: CTA = (qblock 64, head), 128 thr
// ---------------------------------------------------------------------------
#define FA_SMEM (16384 + 2 * 32768)

__device__ __forceinline__ void fa_load(uint32_t sdst, const __nv_bfloat16* g,
                                        int ld, int tid) {
#pragma unroll
    for (int i = 0; i < 4; i++) {
        int cid = i * 128 + tid;
        int row = cid >> 3, c = cid & 7;
        CP16(sdst + row * 128 + ((c ^ (row & 7)) << 4), g + (size_t)row * ld + c * 8);
    }
}

__global__ __launch_bounds__(128)
void k_flash(const __nv_bfloat16* __restrict__ qh, const __nv_bfloat16* __restrict__ ql,
             const __nv_bfloat16* __restrict__ kh, const __nv_bfloat16* __restrict__ kl,
             const __nv_bfloat16* __restrict__ vth, const __nv_bfloat16* __restrict__ vtl,
             __nv_bfloat16* __restrict__ oh, __nv_bfloat16* __restrict__ ol) {
    extern __shared__ char smem[];
    uint32_t sb = smem_u32(smem);
    const int tid = threadIdx.x, w = tid >> 5, lane = tid & 31;
    const int qb = gridDim.x - 1 - blockIdx.x;
    const int hh = blockIdx.y;

    fa_load(sb,        qh + (size_t)(qb * 64) * D + hh * 64, D, tid);
    fa_load(sb + 8192, ql + (size_t)(qb * 64) * D + hh * 64, D, tid);
    {
        uint32_t st = sb + 16384;
        fa_load(st,         kh + hh * 64, D, tid);
        fa_load(st + 8192,  kl + hh * 64, D, tid);
        fa_load(st + 16384, vth + (size_t)(hh * 64) * S, S, tid);
        fa_load(st + 24576, vtl + (size_t)(hh * 64) * S, S, tid);
    }
    CP_COMMIT();

    uint32_t qhf[4][4], qlf[4][4];
    float o_acc[8][4] = {};
    float m0 = -1e30f, m1 = -1e30f, l0 = 0.f, l1 = 0.f;

    for (int kb = 0; kb <= qb; kb++) {
        if (kb + 1 <= qb) {
            uint32_t st = sb + 16384 + ((kb + 1) & 1) * 32768;
            fa_load(st,         kh + (size_t)((kb + 1) * 64) * D + hh * 64, D, tid);
            fa_load(st + 8192,  kl + (size_t)((kb + 1) * 64) * D + hh * 64, D, tid);
            fa_load(st + 16384, vth + (size_t)(hh * 64) * S + (kb + 1) * 64, S, tid);
            fa_load(st + 24576, vtl + (size_t)(hh * 64) * S + (kb + 1) * 64, S, tid);
            CP_COMMIT();
            CP_WAIT(1);
        } else {
            CP_WAIT(0);
        }
        __syncthreads();

        if (kb == 0) {
#pragma unroll
            for (int f = 0; f < 4; f++) {
                int row = w * 16 + (lane & 15);
                int jc = (lane >> 4) + f * 2;
                ldsm4(qhf[f], sb + row * 128 + ((jc ^ (row & 7)) << 4));
                ldsm4(qlf[f], sb + 8192 + row * 128 + ((jc ^ (row & 7)) << 4));
            }
        }

        uint32_t st = sb + 16384 + (kb & 1) * 32768;
        float s_acc[8][4] = {};
#pragma unroll
        for (int ks = 0; ks < 4; ks++) {
            uint32_t bh4[4][4], bl4[4][4];
#pragma unroll
            for (int np = 0; np < 4; np++) {
                int row = np * 16 + ((lane >> 4) << 3) + (lane & 7);
                int jc = ((lane >> 3) & 1) + ks * 2;
                ldsm4(bh4[np], st + row * 128 + ((jc ^ (row & 7)) << 4));
                ldsm4(bl4[np], st + 8192 + row * 128 + ((jc ^ (row & 7)) << 4));
            }
#pragma unroll
            for (int nf = 0; nf < 8; nf++) {
                uint32_t* bh = &bh4[nf >> 1][(nf & 1) * 2];
                uint32_t* bl = &bl4[nf >> 1][(nf & 1) * 2];
                mma_bf16(s_acc[nf], qhf[ks], bh);
                mma_bf16(s_acc[nf], qhf[ks], bl);
                mma_bf16(s_acc[nf], qlf[ks], bh);
            }
        }
        int r_lo = qb * 64 + w * 16 + (lane >> 2);
#pragma unroll
        for (int nf = 0; nf < 8; nf++)
#pragma unroll
            for (int e = 0; e < 4; e++) {
                float v = s_acc[nf][e] * 0.125f;
                if (kb == qb) {
                    int key = kb * 64 + nf * 8 + ((lane & 3) << 1) + (e & 1);
                    int qr = r_lo + ((e >> 1) ? 8 : 0);
                    if (key > qr) v = -1e30f;
                }
                s_acc[nf][e] = v;
            }
        float mx0 = -1e30f, mx1 = -1e30f;
#pragma unroll
        for (int nf = 0; nf < 8; nf++) {
            mx0 = fmaxf(mx0, fmaxf(s_acc[nf][0], s_acc[nf][1]));
            mx1 = fmaxf(mx1, fmaxf(s_acc[nf][2], s_acc[nf][3]));
        }
        mx0 = fmaxf(mx0, __shfl_xor_sync(0xffffffffu, mx0, 1));
        mx0 = fmaxf(mx0, __shfl_xor_sync(0xffffffffu, mx0, 2));
        mx1 = fmaxf(mx1, __shfl_xor_sync(0xffffffffu, mx1, 1));
        mx1 = fmaxf(mx1, __shfl_xor_sync(0xffffffffu, mx1, 2));
        float mn0 = fmaxf(m0, mx0), mn1 = fmaxf(m1, mx1);
        float a0 = __expf(m0 - mn0), a1 = __expf(m1 - mn1);
        float sum0 = 0.f, sum1 = 0.f;
#pragma unroll
        for (int nf = 0; nf < 8; nf++) {
            s_acc[nf][0] = __expf(s_acc[nf][0] - mn0);
            s_acc[nf][1] = __expf(s_acc[nf][1] - mn0);
            s_acc[nf][2] = __expf(s_acc[nf][2] - mn1);
            s_acc[nf][3] = __expf(s_acc[nf][3] - mn1);
            sum0 += s_acc[nf][0] + s_acc[nf][1];
            sum1 += s_acc[nf][2] + s_acc[nf][3];
        }
        sum0 += __shfl_xor_sync(0xffffffffu, sum0, 1);
        sum0 += __shfl_xor_sync(0xffffffffu, sum0, 2);
        sum1 += __shfl_xor_sync(0xffffffffu, sum1, 1);
        sum1 += __shfl_xor_sync(0xffffffffu, sum1, 2);
        l0 = l0 * a0 + sum0;
        l1 = l1 * a1 + sum1;
        m0 = mn0; m1 = mn1;
#pragma unroll
        for (int nf = 0; nf < 8; nf++) {
            o_acc[nf][0] *= a0; o_acc[nf][1] *= a0;
            o_acc[nf][2] *= a1; o_acc[nf][3] *= a1;
        }
        uint32_t pph[4][4], ppl[4][4];
#pragma unroll
        for (int g = 0; g < 4; g++) {
            float c0 = s_acc[2 * g][0], c1 = s_acc[2 * g][1];
            float c2 = s_acc[2 * g][2], c3 = s_acc[2 * g][3];
            float d0 = s_acc[2 * g + 1][0], d1 = s_acc[2 * g + 1][1];
            float d2 = s_acc[2 * g + 1][2], d3 = s_acc[2 * g + 1][3];
            pph[g][0] = pack2bf(c0, c1); pph[g][1] = pack2bf(c2, c3);
            pph[g][2] = pack2bf(d0, d1); pph[g][3] = pack2bf(d2, d3);
            ppl[g][0] = pack2bf(c0 - __bfloat162float(__float2bfloat16(c0)),
                                c1 - __bfloat162float(__float2bfloat16(c1)));
            ppl[g][1] = pack2bf(c2 - __bfloat162float(__float2bfloat16(c2)),
                                c3 - __bfloat162float(__float2bfloat16(c3)));
            ppl[g][2] = pack2bf(d0 - __bfloat162float(__float2bfloat16(d0)),
                                d1 - __bfloat162float(__float2bfloat16(d1)));
            ppl[g][3] = pack2bf(d2 - __bfloat162float(__float2bfloat16(d2)),
                                d3 - __bfloat162float(__float2bfloat16(d3)));
        }
        uint32_t sv = st + 16384;
#pragma unroll
        for (int ks = 0; ks < 4; ks++) {
            uint32_t bh4[4][4], bl4[4][4];
#pragma unroll
            for (int np = 0; np < 4; np++) {
                int row = np * 16 + ((lane >> 4) << 3) + (lane & 7);
                int jc = ((lane >> 3) & 1) + ks * 2;
                ldsm4(bh4[np], sv + row * 128 + ((jc ^ (row & 7)) << 4));
                ldsm4(bl4[np], sv + 8192 + row * 128 + ((jc ^ (row & 7)) << 4));
            }
#pragma unroll
            for (int nf = 0; nf < 8; nf++) {
                uint32_t* bh = &bh4[nf >> 1][(nf & 1) * 2];
                uint32_t* bl = &bl4[nf >> 1][(nf & 1) * 2];
                mma_bf16(o_acc[nf], pph[ks], bh);
                mma_bf16(o_acc[nf], ppl[ks], bh);
                mma_bf16(o_acc[nf], pph[ks], bl);
            }
        }
        __syncthreads();
    }

    float inv0 = 1.f / l0, inv1 = 1.f / l1;
    int row0 = qb * 64 + w * 16 + (lane >> 2);
#pragma unroll
    for (int nf = 0; nf < 8; nf++) {
        int col = hh * 64 + nf * 8 + ((lane & 3) << 1);
        float v0 = o_acc[nf][0] * inv0, v1 = o_acc[nf][1] * inv0;
        float v2 = o_acc[nf][2] * inv1, v3 = o_acc[nf][3] * inv1;
        float h0 = __bfloat162float(__float2bfloat16(v0));
        float h1 = __bfloat162float(__float2bfloat16(v1));
        float h2 = __bfloat162float(__float2bfloat16(v2));
        float h3 = __bfloat162float(__float2bfloat16(v3));
        *(uint32_t*)(oh + (size_t)row0 * D + col) = pack2bf(v0, v1);
        *(uint32_t*)(oh + (size_t)(row0 + 8) * D + col) = pack2bf(v2, v3);
        *(uint32_t*)(ol + (size_t)row0 * D + col) = pack2bf(v0 - h0, v1 - h1);
        *(uint32_t*)(ol + (size_t)(row0 + 8) * D + col) = pack2bf(v2 - h2, v3 - h3);
    }
}

// ---------------------------------------------------------------------------
// flat weight split: 8 elems/thread (R9 config: best measured), grid = n/2048
// ---------------------------------------------------------------------------
__global__ __launch_bounds__(256) void k_split_flat(const float* __restrict__ W,
                                                    __nv_bfloat16* __restrict__ th,
                                                    __nv_bfloat16* __restrict__ tl) {
    size_t gid = (size_t)blockIdx.x * 256 + threadIdx.x;
    float4 a = ((const float4*)W)[2 * gid];
    float4 b = ((const float4*)W)[2 * gid + 1];
    uint4 uh, ul;
    uh.x = pack2bf(a.x, a.y); uh.y = pack2bf(a.z, a.w);
    uh.z = pack2bf(b.x, b.y); uh.w = pack2bf(b.z, b.w);
    ul.x = pack2bf(a.x - __bfloat162float(__float2bfloat16(a.x)),
                   a.y - __bfloat162float(__float2bfloat16(a.y)));
    ul.y = pack2bf(a.z - __bfloat162float(__float2bfloat16(a.z)),
                   a.w - __bfloat162float(__float2bfloat16(a.w)));
    ul.z = pack2bf(b.x - __bfloat162float(__float2bfloat16(b.x)),
                   b.y - __bfloat162float(__float2bfloat16(b.y)));
    ul.w = pack2bf(b.z - __bfloat162float(__float2bfloat16(b.z)),
                   b.w - __bfloat162float(__float2bfloat16(b.w)));
    ((uint4*)th)[gid] = uh;
    ((uint4*)tl)[gid] = ul;
}

// ---------------------------------------------------------------------------
// embedding + positional encoding
// ---------------------------------------------------------------------------
__global__ __launch_bounds__(256) void k_embed(const int* __restrict__ x,
                                               const float* __restrict__ emb,
                                               float* __restrict__ h) {
    int s = blockIdx.y;
    int d = blockIdx.x * 256 + threadIdx.x;
    int tok = x[s];
    float e = emb[(size_t)tok * D + d];
    int i2 = d & ~1;
    float freq = expf((float)i2 * (-9.210340371976184f / (float)D));
    float ang = (float)s * freq;
    float pe = (d & 1) ? cosf(ang) : sinf(ang);
    h[(size_t)s * D + d] = e + pe;
}

// ---------------------------------------------------------------------------
// layernorm -> bf16 hi/lo (warp-shuffle reduce, 1 barrier)
// ---------------------------------------------------------------------------
__global__ __launch_bounds__(256) void k_ln(const float* __restrict__ in,
                                            __nv_bfloat16* __restrict__ oh,
                                            __nv_bfloat16* __restrict__ ol,
                                            const float* __restrict__ w,
                                            const float* __restrict__ b) {
    int row = blockIdx.x;
    const float* xr = in + (size_t)row * D;
    int t = threadIdx.x, wid = t >> 5, lane = t & 31;
    __shared__ float w1s[8], w2s[8];
    float s1 = 0.f, s2 = 0.f;
    for (int d = t; d < D; d += 256) {
        float v = xr[d];
        s1 += v; s2 += v * v;
    }
#pragma unroll
    for (int o = 16; o > 0; o >>= 1) {
        s1 += __shfl_xor_sync(0xffffffffu, s1, o);
        s2 += __shfl_xor_sync(0xffffffffu, s2, o);
    }
    if (lane == 0) { w1s[wid] = s1; w2s[wid] = s2; }
    __syncthreads();
    float t1 = 0.f, t2 = 0.f;
#pragma unroll
    for (int i = 0; i < 8; i++) { t1 += w1s[i]; t2 += w2s[i]; }
    float mean = t1 * (1.0f / D);
    float var = t2 * (1.0f / D) - mean * mean;
    float rstd = rsqrtf(var + EPSF);
    for (int d = t; d < D; d += 256) {
        float v = (xr[d] - mean) * rstd * w[d] + b[d];
        __nv_bfloat16 hv = __float2bfloat16(v);
        oh[(size_t)row * D + d] = hv;
        ol[(size_t)row * D + d] = __float2bfloat16(v - __bfloat162float(hv));
    }
}

// ---------------------------------------------------------------------------
// launch orchestration (two streams: s1 compute, s2 weight prep)
// ---------------------------------------------------------------------------
extern "C" void kernel_launch(void* const* d_in, const int* in_sizes, int n_in,
                              void* d_out, int out_size) {
    (void)in_sizes; (void)n_in; (void)out_size;
    const int*   x      = (const int*)d_in[0];
    const float* emb    = (const float*)d_in[1];
    const float* Wq     = (const float*)d_in[2];
    const float* Wk     = (const float*)d_in[3];
    const float* Wv     = (const float*)d_in[4];
    const float* Wo     = (const float*)d_in[5];
    const float* bo     = (const float*)d_in[6];
    const float* ln1_w  = (const float*)d_in[7];
    const float* ln1_b  = (const float*)d_in[8];
    const float* W1     = (const float*)d_in[9];
    const float* b1     = (const float*)d_in[10];
    const float* W2     = (const float*)d_in[11];
    const float* b2     = (const float*)d_in[12];
    const float* ln2_w  = (const float*)d_in[13];
    const float* ln2_b  = (const float*)d_in[14];
    const float* fn_w   = (const float*)d_in[15];
    const float* fn_b   = (const float*)d_in[16];
    const float* lmhead = (const float*)d_in[17];
    float* out = (float*)d_out;

    static float* ph = nullptr;
    static __nv_bfloat16 *acth, *actl, *ffh, *ffl, *qh, *ql, *kh, *kl, *vth, *vtl,
                         *qkvh, *qkvl, *woh, *wol, *w1h, *w1l, *w2h, *w2l, *lmh, *lml;
    static cudaStream_t s1, s2;
    static cudaEvent_t evFork, evW[L], evLM, evDone;
    if (!ph) {
        cudaGetSymbolAddress((void**)&ph,   g_h);
        cudaGetSymbolAddress((void**)&acth, g_act_h);
        cudaGetSymbolAddress((void**)&actl, g_act_l);
        cudaGetSymbolAddress((void**)&ffh,  g_ff_h);
        cudaGetSymbolAddress((void**)&ffl,  g_ff_l);
        cudaGetSymbolAddress((void**)&qh,   g_qh);
        cudaGetSymbolAddress((void**)&ql,   g_ql);
        cudaGetSymbolAddress((void**)&kh,   g_kh);
        cudaGetSymbolAddress((void**)&kl,   g_kl);
        cudaGetSymbolAddress((void**)&vth,  g_vth);
        cudaGetSymbolAddress((void**)&vtl,  g_vtl);
        cudaGetSymbolAddress((void**)&qkvh, g_qkv_h);
        cudaGetSymbolAddress((void**)&qkvl, g_qkv_l);
        cudaGetSymbolAddress((void**)&woh,  g_wo_h);
        cudaGetSymbolAddress((void**)&wol,  g_wo_l);
        cudaGetSymbolAddress((void**)&w1h,  g_w1_h);
        cudaGetSymbolAddress((void**)&w1l,  g_w1_l);
        cudaGetSymbolAddress((void**)&w2h,  g_w2_h);
        cudaGetSymbolAddress((void**)&w2l,  g_w2_l);
        cudaGetSymbolAddress((void**)&lmh,  g_lm_h);
        cudaGetSymbolAddress((void**)&lml,  g_lm_l);
        cudaFuncSetAttribute(k_gemm_f32,     cudaFuncAttributeMaxDynamicSharedMemorySize, MG_SMEM);
        cudaFuncSetAttribute(k_gemm_f32_t64, cudaFuncAttributeMaxDynamicSharedMemorySize, T64_SMEM);
        cudaFuncSetAttribute(k_gemm_bf16,    cudaFuncAttributeMaxDynamicSharedMemorySize, MG_SMEM);
        cudaFuncSetAttribute(k_qkv_gemm,     cudaFuncAttributeMaxDynamicSharedMemorySize, MG_SMEM);
        cudaFuncSetAttribute(k_flash,        cudaFuncAttributeMaxDynamicSharedMemorySize, FA_SMEM);
        cudaStreamCreateWithFlags(&s1, cudaStreamNonBlocking);
        cudaStreamCreateWithFlags(&s2, cudaStreamNonBlocking);
        cudaEventCreateWithFlags(&evFork, cudaEventDisableTiming);
        for (int l = 0; l < L; l++) cudaEventCreateWithFlags(&evW[l], cudaEventDisableTiming);
        cudaEventCreateWithFlags(&evLM, cudaEventDisableTiming);
        cudaEventCreateWithFlags(&evDone, cudaEventDisableTiming);
    }

    // fork
    cudaEventRecord(evFork, 0);
    cudaStreamWaitEvent(s1, evFork, 0);
    cudaStreamWaitEvent(s2, evFork, 0);

    // s2: weight prep (8 elts/thread; grid = n/2048)
    const int gDD = D * D / 2048;
    const int gDF = D * FF / 2048;
    for (int l = 0; l < L; l++) {
        size_t wo = (size_t)l * D * D;
        size_t qo = (size_t)l * 3 * D * D;
        k_split_flat<<<gDD, 256, 0, s2>>>(Wq + wo, qkvh + qo,             qkvl + qo);
        k_split_flat<<<gDD, 256, 0, s2>>>(Wk + wo, qkvh + qo + D * D,     qkvl + qo + D * D);
        k_split_flat<<<gDD, 256, 0, s2>>>(Wv + wo, qkvh + qo + 2 * D * D, qkvl + qo + 2 * D * D);
        k_split_flat<<<gDD, 256, 0, s2>>>(Wo + wo, woh + wo, wol + wo);
        k_split_flat<<<gDF, 256, 0, s2>>>(W1 + (size_t)l * D * FF,
                                          w1h + (size_t)l * D * FF, w1l + (size_t)l * D * FF);
        k_split_flat<<<gDF, 256, 0, s2>>>(W2 + (size_t)l * FF * D,
                                          w2h + (size_t)l * FF * D, w2l + (size_t)l * FF * D);
        cudaEventRecord(evW[l], s2);
    }
    k_split_flat<<<(int)((size_t)D * V / 2048), 256, 0, s2>>>(lmhead, lmh, lml);
    cudaEventRecord(evLM, s2);

    // s1: compute
    k_embed<<<dim3(D / 256, S), 256, 0, s1>>>(x, emb, ph);

    for (int l = 0; l < L; l++) {
        size_t wo = (size_t)l * D * D;
        size_t qo = (size_t)l * 3 * D * D;
        cudaStreamWaitEvent(s1, evW[l], 0);
        // --- attention ---
        k_ln<<<S, 256, 0, s1>>>(ph, acth, actl, ln1_w + (size_t)l * D, ln1_b + (size_t)l * D);
        k_qkv_gemm<<<dim3(3 * D / 128, S / 128), 256, MG_SMEM, s1>>>(
            acth, actl, qkvh + qo, qkvl + qo, qh, ql, kh, kl, vth, vtl);
        k_flash<<<dim3(S / 64, H), 128, FA_SMEM, s1>>>(qh, ql, kh, kl, vth, vtl, acth, actl);
        k_gemm_f32_t64<<<dim3(D / 64, S / 64), 256, T64_SMEM, s1>>>(
            acth, actl, woh + wo, wol + wo, bo + (size_t)l * D, ph, ph, D, D, D);
        // --- FFN ---
        k_ln<<<S, 256, 0, s1>>>(ph, acth, actl, ln2_w + (size_t)l * D, ln2_b + (size_t)l * D);
        k_gemm_bf16<<<dim3(FF / 128, S / 128), 256, MG_SMEM, s1>>>(
            acth, actl, w1h + (size_t)l * D * FF, w1l + (size_t)l * D * FF,
            b1 + (size_t)l * FF, ffh, ffl, D, FF, FF, 1);
        k_gemm_f32_t64<<<dim3(D / 64, S / 64), 256, T64_SMEM, s1>>>(
            ffh, ffl, w2h + (size_t)l * FF * D, w2l + (size_t)l * FF * D,
            b2 + (size_t)l * D, ph, ph, FF, D, D);
    }

    // final LN + LM head
    cudaStreamWaitEvent(s1, evLM, 0);
    k_ln<<<S, 256, 0, s1>>>(ph, acth, actl, fn_w, fn_b);
    k_gemm_f32<<<dim3(V / 128, S / 128), 256, MG_SMEM, s1>>>(
        acth, actl, lmh, lml, nullptr, nullptr, out, D, V, V);

    // join
    cudaEventRecord(evDone, s1);
    cudaStreamWaitEvent(0, evDone, 0);
}